// round 11
// baseline (speedup 1.0000x reference)
#include <cuda_runtime.h>
#include <math.h>
#include <stdint.h>

// Problem constants
#define B_   4
#define T_   4096
#define D_   1024
#define H_   16
#define HD   64
#define BT   (B_*T_)      // 16384
#define BH   (B_*H_)      // 64
#define NKV  3072
#define NCHUNK 32
#define CHLEN (T_/NCHUNK) // 128
#define GK   1024

// Scratch
__device__ float g_qf [BH*T_*HD];
__device__ float g_kf [BH*T_*HD];
__device__ float g_v  [BH*T_*HD];
__device__ float g_kvp[NCHUNK*BH*HD*HD];
__device__ float g_kv [BH*HD*HD];
__device__ float g_ksp[NCHUNK*BH*HD];
__device__ float g_ksum[BH*HD];
__device__ float g_attn[BT*D_];
__device__ float g_xa  [BT*D_];
__device__ float g_wqT [NKV*D_];
__device__ float g_woT [D_*D_];
__device__ float g_cos[T_*32];
__device__ float g_sin[T_*32];

// ---------------------------------------------------------------------------
__device__ __forceinline__ uint32_t smem_u32(const void* p) {
    uint32_t a;
    asm("{ .reg .u64 t; cvta.to.shared.u64 t, %1; cvt.u32.u64 %0, t; }"
        : "=r"(a) : "l"(p));
    return a;
}
__device__ __forceinline__ float tf32r(float x) {
    uint32_t o;
    asm("cvt.rna.tf32.f32 %0, %1;" : "=r"(o) : "f"(x));
    return __uint_as_float(o);
}
#define CP_ASYNC16(dst, src) \
    asm volatile("cp.async.cg.shared.global [%0], [%1], 16;" :: "r"(dst), "l"(src) : "memory")
#define CP_COMMIT()  asm volatile("cp.async.commit_group;" ::: "memory")
#define CP_WAIT2()   asm volatile("cp.async.wait_group 2;" ::: "memory")

__device__ __forceinline__ void ldsm_x4(uint32_t* r, uint32_t addr) {
    asm volatile("ldmatrix.sync.aligned.m8n8.x4.shared.b16 {%0,%1,%2,%3}, [%4];"
        : "=r"(r[0]), "=r"(r[1]), "=r"(r[2]), "=r"(r[3]) : "r"(addr));
}
__device__ __forceinline__ void mma_tf32(float* d, const uint32_t* a, const uint32_t* b) {
    asm volatile(
        "mma.sync.aligned.m16n8k8.row.col.f32.tf32.tf32.f32 "
        "{%0,%1,%2,%3}, {%4,%5,%6,%7}, {%8,%9}, {%0,%1,%2,%3};"
        : "+f"(d[0]), "+f"(d[1]), "+f"(d[2]), "+f"(d[3])
        : "r"(a[0]), "r"(a[1]), "r"(a[2]), "r"(a[3]),
          "r"(b[0]), "r"(b[1]));
}
__device__ __forceinline__ float elu1(float x) {
    return x > 0.f ? x + 1.f : expf(x);
}

// ---------------------------------------------------------------------------
// tf32 mma.sync GEMM (R6 config — best measured): 128x128 CTA tile, BK=16,
// 4-stage cp.async (wait_group 2) + barrier, 256 threads, warp tile 32x64,
// ldmatrix fragment loads, ROWF=20 padding (conflict-free).
// mode 0: plain C store. mode 1: fused RoPE/elu qkv epilogue.
// ---------------------------------------------------------------------------
#define STAGES 4
#define ROWF   20
#define STG_F  (128*ROWF)
#define GEMM_SMEM (2*STAGES*STG_F*4)    // 81920 B

__global__ __launch_bounds__(256, 2)
void gemm_tf32_kernel(int N, int mode, const float* __restrict__ A,
                      const float* __restrict__ Bt, float* __restrict__ C) {
    extern __shared__ float sm[];
    float* As = sm;
    float* Bs = sm + STAGES*STG_F;

    const int tid  = threadIdx.x;
    const int wid  = tid >> 5;
    const int lane = tid & 31;
    const int g    = lane >> 2;
    const int tg   = lane & 3;
    const int lrow = lane & 7;
    const int seg  = lane >> 3;      // 0..3

    const int rowBase = blockIdx.y * 128;
    const int colBase = blockIdx.x * 128;
    const int mBase = (wid & 3) * 32;
    const int nBase = (wid >> 2) * 64;

    // cp.async mapping: 2 threads per row, 8 floats (2x16B) each
    const int lr = tid >> 1;
    const int lc = (tid & 1) * 8;
    const float* aSrc = A  + (size_t)(rowBase + lr)*GK + lc;
    const float* bSrc = Bt + (size_t)(colBase + lr)*GK + lc;
    const uint32_t aDst = smem_u32(As) + (uint32_t)(lr*ROWF + lc)*4;
    const uint32_t bDst = smem_u32(Bs) + (uint32_t)(lr*ROWF + lc)*4;

    // ldmatrix per-lane base addresses
    const uint32_t aFrag0 = smem_u32(As) +
        (uint32_t)(((mBase + (seg & 1)*8 + lrow)*ROWF + (seg >> 1)*4) * 4);
    const uint32_t bFrag0 = smem_u32(Bs) +
        (uint32_t)(((nBase + (seg >> 1)*8 + lrow)*ROWF + (seg & 1)*4) * 4);

    float acc[2][8][4];
    #pragma unroll
    for (int mt = 0; mt < 2; mt++)
        #pragma unroll
        for (int nt = 0; nt < 8; nt++)
            #pragma unroll
            for (int q = 0; q < 4; q++) acc[mt][nt][q] = 0.f;

    // prologue: stages 0..2
    #pragma unroll
    for (int s = 0; s < STAGES-1; s++) {
        const uint32_t so = (uint32_t)s * (STG_F*4);
        const float* ap = aSrc + s*16;
        const float* bp = bSrc + s*16;
        CP_ASYNC16(aDst + so,      ap);
        CP_ASYNC16(aDst + so + 16, ap + 4);
        CP_ASYNC16(bDst + so,      bp);
        CP_ASYNC16(bDst + so + 16, bp + 4);
        CP_COMMIT();
    }

    const int NIT = GK / 16;   // 64
    for (int it = 0; it < NIT; it++) {
        CP_WAIT2();
        __syncthreads();

        const int nit = it + STAGES - 1;
        if (nit < NIT) {
            const int s = nit % STAGES;
            const uint32_t so = (uint32_t)s * (STG_F*4);
            const float* ap = aSrc + nit*16;
            const float* bp = bSrc + nit*16;
            CP_ASYNC16(aDst + so,      ap);
            CP_ASYNC16(aDst + so + 16, ap + 4);
            CP_ASYNC16(bDst + so,      bp);
            CP_ASYNC16(bDst + so + 16, bp + 4);
        }
        CP_COMMIT();

        const uint32_t so = (uint32_t)(it % STAGES) * (STG_F*4);
        const uint32_t aF = aFrag0 + so;
        const uint32_t bF = bFrag0 + so;
        #pragma unroll
        for (int ks = 0; ks < 16; ks += 8) {
            uint32_t af[2][4];
            uint32_t bf[4][4];   // pair p covers n-tiles 2p, 2p+1
            ldsm_x4(af[0], aF             + ks*4);
            ldsm_x4(af[1], aF + 16*ROWF*4 + ks*4);
            #pragma unroll
            for (int p = 0; p < 4; p++)
                ldsm_x4(bf[p], bF + p*16*ROWF*4 + ks*4);
            #pragma unroll
            for (int mt = 0; mt < 2; mt++)
                #pragma unroll
                for (int nt = 0; nt < 8; nt++)
                    mma_tf32(acc[mt][nt], af[mt], &bf[nt >> 1][(nt & 1)*2]);
        }
    }

    if (mode == 0) {
        #pragma unroll
        for (int mt = 0; mt < 2; mt++) {
            const int r0 = rowBase + mBase + mt*16 + g;
            #pragma unroll
            for (int nt = 0; nt < 8; nt++) {
                const int c0 = colBase + nBase + nt*8 + tg*2;
                *(float2*)&C[(size_t) r0   *N + c0] = make_float2(acc[mt][nt][0], acc[mt][nt][1]);
                *(float2*)&C[(size_t)(r0+8)*N + c0] = make_float2(acc[mt][nt][2], acc[mt][nt][3]);
            }
        }
    } else {
        // fused qkv epilogue. Warp's 64 cols = one head of q, k, or v.
        const int region = colBase >> 10;            // 0=q 1=k 2=v
        float* dst = (region == 0) ? g_qf : (region == 1 ? g_kf : g_v);
        const int head = (((colBase & 1023) + nBase) >> 6);
        #pragma unroll
        for (int mt = 0; mt < 2; mt++) {
            #pragma unroll
            for (int half = 0; half < 2; half++) {
                const int row = rowBase + mBase + mt*16 + g + half*8;
                const int t = row & (T_-1);
                const int b = row >> 12;
                const size_t obase = ((size_t)(b*H_ + head)*T_ + t)*HD;
                #pragma unroll
                for (int nt = 0; nt < 4; nt++) {
                    const int i0 = nt*8 + tg*2;
                    const float a0 = acc[mt][nt  ][half*2+0];
                    const float a1 = acc[mt][nt  ][half*2+1];
                    const float b0 = acc[mt][nt+4][half*2+0];
                    const float b1 = acc[mt][nt+4][half*2+1];
                    if (region == 2) {
                        *(float2*)&dst[obase + i0]      = make_float2(a0, a1);
                        *(float2*)&dst[obase + i0 + 32] = make_float2(b0, b1);
                    } else {
                        const float2 cc = *(const float2*)&g_cos[t*32 + i0];
                        const float2 ss = *(const float2*)&g_sin[t*32 + i0];
                        float r10 = a0*cc.x - b0*ss.x, r20 = b0*cc.x + a0*ss.x;
                        float r11 = a1*cc.y - b1*ss.y, r21 = b1*cc.y + a1*ss.y;
                        if (region == 0) {
                            r10 *= 0.125f; r20 *= 0.125f; r11 *= 0.125f; r21 *= 0.125f;
                        }
                        *(float2*)&dst[obase + i0]      = make_float2(elu1(r10), elu1(r11));
                        *(float2*)&dst[obase + i0 + 32] = make_float2(elu1(r20), elu1(r21));
                    }
                }
            }
        }
    }
}

// ---------------------------------------------------------------------------
// merged prep: blocks [0, RX_BLOCKS) do round_x; the rest do RoPE tables
// ---------------------------------------------------------------------------
#define RX_BLOCKS (BT*D_/4/256)     // 16384
#define RT_BLOCKS (T_*32/256)       // 512

__global__ __launch_bounds__(256)
void prep_kernel(const float* __restrict__ x) {
    if (blockIdx.x < RX_BLOCKS) {
        int i = blockIdx.x * 256 + threadIdx.x;
        float4 v = ((const float4*)x)[i];
        v.x = tf32r(v.x); v.y = tf32r(v.y); v.z = tf32r(v.z); v.w = tf32r(v.w);
        ((float4*)g_xa)[i] = v;
    } else {
        int idx = (blockIdx.x - RX_BLOCKS) * 256 + threadIdx.x;
        int t = idx >> 5;
        int i = idx & 31;
        float inv = powf(500000.0f, -(float)i * (1.0f/32.0f));
        float a = (float)t * inv;
        g_cos[idx] = cosf(a);
        g_sin[idx] = sinf(a);
    }
}

// both weight transposes in ONE launch
__global__ __launch_bounds__(256)
void transpose_round_kernel(const float* __restrict__ wq, const float* __restrict__ wo) {
    __shared__ float tile[32][33];
    const int R = D_;
    const float* in; float* out; int Cc; int bx;
    if (blockIdx.x < NKV/32) { in = wq; out = g_wqT; Cc = NKV; bx = blockIdx.x * 32; }
    else                     { in = wo; out = g_woT; Cc = D_;  bx = (blockIdx.x - NKV/32) * 32; }
    int by = blockIdx.y * 32;
    int tx = threadIdx.x, ty = threadIdx.y;
    #pragma unroll
    for (int i = 0; i < 32; i += 8)
        tile[ty + i][tx] = in[(size_t)(by + ty + i) * Cc + bx + tx];
    __syncthreads();
    #pragma unroll
    for (int i = 0; i < 32; i += 8)
        out[(size_t)(bx + ty + i) * R + by + tx] = tf32r(tile[tx][ty + i]);
}

// ---------------------------------------------------------------------------
// kv partial accumulation (R10 config — best measured): 128 threads,
// 8x4 register microtile, NCHUNK=32
// ---------------------------------------------------------------------------
__global__ __launch_bounds__(128)
void kv_accum_kernel() {
    int blk = blockIdx.x;
    int bh  = blk >> 5;
    int c   = blk & 31;
    int tid = threadIdx.x;
    int d0  = (tid >> 4) * 8;     // 0..56
    int j0  = (tid & 15) * 4;     // 0..60

    __shared__ float kb[16][64];
    __shared__ float vb[16][64];

    float acc[8][4] = {};
    float ks[8] = {};

    int t0 = c * CHLEN;
    for (int tb = 0; tb < CHLEN; tb += 16) {
        #pragma unroll
        for (int u = 0; u < 2; u++) {
            int f  = tid + u*128;
            int rr = f >> 4, c4 = f & 15;
            int t  = t0 + tb + rr;
            *(float4*)&kb[rr][c4*4] =
                *(const float4*)&g_kf[((size_t)bh*T_ + t)*HD + c4*4];
            *(float4*)&vb[rr][c4*4] =
                *(const float4*)&g_v[((size_t)bh*T_ + t)*HD + c4*4];
        }
        __syncthreads();
        #pragma unroll
        for (int tt = 0; tt < 16; tt++) {
            float kk[8], vv[4];
            *(float4*)&kk[0] = *(float4*)&kb[tt][d0];
            *(float4*)&kk[4] = *(float4*)&kb[tt][d0+4];
            *(float4*)&vv[0] = *(float4*)&vb[tt][j0];
            #pragma unroll
            for (int i = 0; i < 8; i++) {
                ks[i] += kk[i];
                #pragma unroll
                for (int j = 0; j < 4; j++)
                    acc[i][j] += kk[i] * vv[j];
            }
        }
        __syncthreads();
    }

    #pragma unroll
    for (int i = 0; i < 8; i++) {
        float* p = &g_kvp[((size_t)(c*BH + bh)*HD + d0 + i)*HD + j0];
        *(float4*)p = make_float4(acc[i][0], acc[i][1], acc[i][2], acc[i][3]);
    }
    if ((tid & 15) == 0) {
        #pragma unroll
        for (int i = 0; i < 8; i++)
            g_ksp[(c*BH + bh)*HD + d0 + i] = ks[i];
    }
}

__global__ void kv_reduce_kernel() {
    int idx = blockIdx.x * 256 + threadIdx.x;
    if (idx < BH*HD*HD) {
        float s = 0.f;
        #pragma unroll
        for (int c = 0; c < NCHUNK; c++) s += g_kvp[(size_t)c*BH*HD*HD + idx];
        g_kv[idx] = s;
    }
    if (idx < BH*HD) {
        float s = 0.f;
        #pragma unroll
        for (int c = 0; c < NCHUNK; c++) s += g_ksp[c*BH*HD + idx];
        g_ksum[idx] = s;
    }
}

// ---------------------------------------------------------------------------
__global__ __launch_bounds__(256)
void attn_out_kernel() {
    int blk = blockIdx.x;
    int bh  = blk >> 6;
    int tc  = blk & 63;
    int b   = bh >> 4;
    int h   = bh & 15;
    int tid = threadIdx.x;

    __shared__ float skv[HD*HD];
    __shared__ float sks[HD];
    __shared__ float sqf[64*HD];

    #pragma unroll
    for (int u = 0; u < 16; u++) {
        int li = tid + u*256;
        skv[li] = g_kv[bh*HD*HD + li];
        sqf[li] = g_qf[((size_t)bh*T_ + tc*64)*HD + li];
    }
    if (tid < 64) sks[tid] = g_ksum[bh*HD + tid];
    __syncthreads();

    int tl = tid >> 2;
    int jb = (tid & 3) << 4;

    float den = 0.f;
    #pragma unroll
    for (int dd = 0; dd < 64; dd++) den += sqf[tl*64 + dd] * sks[dd];
    float sc = 1.f / fmaxf(den, 1e-6f);

    float4 acc[4] = {};
    #pragma unroll
    for (int dd = 0; dd < 64; dd++) {
        float qd = sqf[tl*64 + dd];
        const float4* kvr = (const float4*)&skv[dd*64 + jb];
        #pragma unroll
        for (int j4 = 0; j4 < 4; j4++) {
            float4 kk = kvr[j4];
            acc[j4].x += qd * kk.x;
            acc[j4].y += qd * kk.y;
            acc[j4].z += qd * kk.z;
            acc[j4].w += qd * kk.w;
        }
    }

    int t = tc*64 + tl;
    float* outp = &g_attn[((size_t)(b*T_ + t))*D_ + h*HD + jb];
    #pragma unroll
    for (int j4 = 0; j4 < 4; j4++) {
        float4 v = make_float4(tf32r(acc[j4].x*sc), tf32r(acc[j4].y*sc),
                               tf32r(acc[j4].z*sc), tf32r(acc[j4].w*sc));
        *(float4*)&outp[j4*4] = v;
    }
}

// ---------------------------------------------------------------------------
extern "C" void kernel_launch(void* const* d_in, const int* in_sizes, int n_in,
                              void* d_out, int out_size) {
    const float* x = nullptr; const float* Wqkv = nullptr; const float* Wout = nullptr;
    for (int i = 0; i < n_in; i++) {
        if (in_sizes[i] == BT*D_)       x    = (const float*)d_in[i];
        else if (in_sizes[i] == D_*NKV) Wqkv = (const float*)d_in[i];
        else if (in_sizes[i] == D_*D_)  Wout = (const float*)d_in[i];
    }
    float* out = (float*)d_out;

    float *attn_p, *xa_p, *wqT_p, *woT_p;
    cudaGetSymbolAddress((void**)&attn_p, g_attn);
    cudaGetSymbolAddress((void**)&xa_p,   g_xa);
    cudaGetSymbolAddress((void**)&wqT_p,  g_wqT);
    cudaGetSymbolAddress((void**)&woT_p,  g_woT);

    cudaFuncSetAttribute(gemm_tf32_kernel,
                         cudaFuncAttributeMaxDynamicSharedMemorySize, GEMM_SMEM);

    // launch 0: merged prep (tf32 round of x + fp32 RoPE tables)
    prep_kernel<<<RX_BLOCKS + RT_BLOCKS, 256>>>(x);
    // launch 1: weight transposes
    transpose_round_kernel<<<dim3(NKV/32 + D_/32, D_/32), dim3(32, 8)>>>(Wqkv, Wout);

    // launch 2: qkv GEMM with fused RoPE + feature-map epilogue
    gemm_tf32_kernel<<<dim3(NKV/128, BT/128), 256, GEMM_SMEM>>>(NKV, 1, xa_p, wqT_p, nullptr);

    // launch 3,4: kv & ksum
    kv_accum_kernel<<<BH*NCHUNK, 128>>>();
    kv_reduce_kernel<<<(BH*HD*HD)/256, 256>>>();

    // launch 5: attention epilogue
    attn_out_kernel<<<BH*64, 256>>>();

    // launch 6: out = attn @ W_out
    gemm_tf32_kernel<<<dim3(D_/128, BT/128), 256, GEMM_SMEM>>>(D_, 0, attn_p, woT_p, out);
}

// round 12
// speedup vs baseline: 1.5619x; 1.5619x over previous
#include <cuda_runtime.h>
#include <math.h>
#include <stdint.h>

// Problem constants
#define B_   4
#define T_   4096
#define D_   1024
#define H_   16
#define HD   64
#define BT   (B_*T_)      // 16384
#define BH   (B_*H_)      // 64
#define NKV  3072
#define NCHUNK 32
#define CHLEN (T_/NCHUNK) // 128
#define GK   1024

// Scratch
__device__ float g_qf [BH*T_*HD];
__device__ float g_kf [BH*T_*HD];
__device__ float g_v  [BH*T_*HD];
__device__ float g_kvp[NCHUNK*BH*HD*HD];
__device__ float g_kv [BH*HD*HD];
__device__ float g_ksp[NCHUNK*BH*HD];
__device__ float g_ksum[BH*HD];
__device__ float g_attn[BT*D_];
__device__ float g_xa  [BT*D_];
__device__ float g_wqT [NKV*D_];
__device__ float g_woT [D_*D_];
__device__ float g_cos[T_*32];
__device__ float g_sin[T_*32];

// ---------------------------------------------------------------------------
__device__ __forceinline__ uint32_t smem_u32(const void* p) {
    uint32_t a;
    asm("{ .reg .u64 t; cvta.to.shared.u64 t, %1; cvt.u32.u64 %0, t; }"
        : "=r"(a) : "l"(p));
    return a;
}
__device__ __forceinline__ float tf32r(float x) {
    uint32_t o;
    asm("cvt.rna.tf32.f32 %0, %1;" : "=r"(o) : "f"(x));
    return __uint_as_float(o);
}
#define CP_ASYNC16(dst, src) \
    asm volatile("cp.async.cg.shared.global [%0], [%1], 16;" :: "r"(dst), "l"(src) : "memory")
#define CP_COMMIT()  asm volatile("cp.async.commit_group;" ::: "memory")
#define CP_WAIT2()   asm volatile("cp.async.wait_group 2;" ::: "memory")

__device__ __forceinline__ void ldsm_x4(uint32_t* r, uint32_t addr) {
    asm volatile("ldmatrix.sync.aligned.m8n8.x4.shared.b16 {%0,%1,%2,%3}, [%4];"
        : "=r"(r[0]), "=r"(r[1]), "=r"(r[2]), "=r"(r[3]) : "r"(addr));
}
__device__ __forceinline__ void mma_tf32(float* d, const uint32_t* a, const uint32_t* b) {
    asm volatile(
        "mma.sync.aligned.m16n8k8.row.col.f32.tf32.tf32.f32 "
        "{%0,%1,%2,%3}, {%4,%5,%6,%7}, {%8,%9}, {%0,%1,%2,%3};"
        : "+f"(d[0]), "+f"(d[1]), "+f"(d[2]), "+f"(d[3])
        : "r"(a[0]), "r"(a[1]), "r"(a[2]), "r"(a[3]),
          "r"(b[0]), "r"(b[1]));
}
__device__ __forceinline__ float elu1(float x) {
    return x > 0.f ? x + 1.f : expf(x);
}

// ---------------------------------------------------------------------------
// tf32 mma.sync GEMM (R6 config — best measured): 128x128 CTA tile, BK=16,
// 4-stage cp.async (wait_group 2) + barrier, 256 threads, warp tile 32x64,
// ldmatrix fragment loads, ROWF=20 padding (conflict-free).
// mode 0: plain C store. mode 1: fused RoPE/elu qkv epilogue.
// ---------------------------------------------------------------------------
#define STAGES 4
#define ROWF   20
#define STG_F  (128*ROWF)
#define GEMM_SMEM (2*STAGES*STG_F*4)    // 81920 B

__global__ __launch_bounds__(256, 2)
void gemm_tf32_kernel(int N, int mode, const float* __restrict__ A,
                      const float* __restrict__ Bt, float* __restrict__ C) {
    extern __shared__ float sm[];
    float* As = sm;
    float* Bs = sm + STAGES*STG_F;

    const int tid  = threadIdx.x;
    const int wid  = tid >> 5;
    const int lane = tid & 31;
    const int g    = lane >> 2;
    const int tg   = lane & 3;
    const int lrow = lane & 7;
    const int seg  = lane >> 3;      // 0..3

    const int rowBase = blockIdx.y * 128;
    const int colBase = blockIdx.x * 128;
    const int mBase = (wid & 3) * 32;
    const int nBase = (wid >> 2) * 64;

    // cp.async mapping: 2 threads per row, 8 floats (2x16B) each
    const int lr = tid >> 1;
    const int lc = (tid & 1) * 8;
    const float* aSrc = A  + (size_t)(rowBase + lr)*GK + lc;
    const float* bSrc = Bt + (size_t)(colBase + lr)*GK + lc;
    const uint32_t aDst = smem_u32(As) + (uint32_t)(lr*ROWF + lc)*4;
    const uint32_t bDst = smem_u32(Bs) + (uint32_t)(lr*ROWF + lc)*4;

    // ldmatrix per-lane base addresses
    const uint32_t aFrag0 = smem_u32(As) +
        (uint32_t)(((mBase + (seg & 1)*8 + lrow)*ROWF + (seg >> 1)*4) * 4);
    const uint32_t bFrag0 = smem_u32(Bs) +
        (uint32_t)(((nBase + (seg >> 1)*8 + lrow)*ROWF + (seg & 1)*4) * 4);

    float acc[2][8][4];
    #pragma unroll
    for (int mt = 0; mt < 2; mt++)
        #pragma unroll
        for (int nt = 0; nt < 8; nt++)
            #pragma unroll
            for (int q = 0; q < 4; q++) acc[mt][nt][q] = 0.f;

    // prologue: stages 0..2
    #pragma unroll
    for (int s = 0; s < STAGES-1; s++) {
        const uint32_t so = (uint32_t)s * (STG_F*4);
        const float* ap = aSrc + s*16;
        const float* bp = bSrc + s*16;
        CP_ASYNC16(aDst + so,      ap);
        CP_ASYNC16(aDst + so + 16, ap + 4);
        CP_ASYNC16(bDst + so,      bp);
        CP_ASYNC16(bDst + so + 16, bp + 4);
        CP_COMMIT();
    }

    const int NIT = GK / 16;   // 64
    for (int it = 0; it < NIT; it++) {
        CP_WAIT2();
        __syncthreads();

        const int nit = it + STAGES - 1;
        if (nit < NIT) {
            const int s = nit % STAGES;
            const uint32_t so = (uint32_t)s * (STG_F*4);
            const float* ap = aSrc + nit*16;
            const float* bp = bSrc + nit*16;
            CP_ASYNC16(aDst + so,      ap);
            CP_ASYNC16(aDst + so + 16, ap + 4);
            CP_ASYNC16(bDst + so,      bp);
            CP_ASYNC16(bDst + so + 16, bp + 4);
        }
        CP_COMMIT();

        const uint32_t so = (uint32_t)(it % STAGES) * (STG_F*4);
        const uint32_t aF = aFrag0 + so;
        const uint32_t bF = bFrag0 + so;
        #pragma unroll
        for (int ks = 0; ks < 16; ks += 8) {
            uint32_t af[2][4];
            uint32_t bf[4][4];   // pair p covers n-tiles 2p, 2p+1
            ldsm_x4(af[0], aF             + ks*4);
            ldsm_x4(af[1], aF + 16*ROWF*4 + ks*4);
            #pragma unroll
            for (int p = 0; p < 4; p++)
                ldsm_x4(bf[p], bF + p*16*ROWF*4 + ks*4);
            #pragma unroll
            for (int mt = 0; mt < 2; mt++)
                #pragma unroll
                for (int nt = 0; nt < 8; nt++)
                    mma_tf32(acc[mt][nt], af[mt], &bf[nt >> 1][(nt & 1)*2]);
        }
    }

    if (mode == 0) {
        #pragma unroll
        for (int mt = 0; mt < 2; mt++) {
            const int r0 = rowBase + mBase + mt*16 + g;
            #pragma unroll
            for (int nt = 0; nt < 8; nt++) {
                const int c0 = colBase + nBase + nt*8 + tg*2;
                *(float2*)&C[(size_t) r0   *N + c0] = make_float2(acc[mt][nt][0], acc[mt][nt][1]);
                *(float2*)&C[(size_t)(r0+8)*N + c0] = make_float2(acc[mt][nt][2], acc[mt][nt][3]);
            }
        }
    } else {
        // fused qkv epilogue. Warp's 64 cols = one head of q, k, or v.
        const int region = colBase >> 10;            // 0=q 1=k 2=v
        float* dst = (region == 0) ? g_qf : (region == 1 ? g_kf : g_v);
        const int head = (((colBase & 1023) + nBase) >> 6);
        #pragma unroll
        for (int mt = 0; mt < 2; mt++) {
            #pragma unroll
            for (int half = 0; half < 2; half++) {
                const int row = rowBase + mBase + mt*16 + g + half*8;
                const int t = row & (T_-1);
                const int b = row >> 12;
                const size_t obase = ((size_t)(b*H_ + head)*T_ + t)*HD;
                #pragma unroll
                for (int nt = 0; nt < 4; nt++) {
                    const int i0 = nt*8 + tg*2;
                    const float a0 = acc[mt][nt  ][half*2+0];
                    const float a1 = acc[mt][nt  ][half*2+1];
                    const float b0 = acc[mt][nt+4][half*2+0];
                    const float b1 = acc[mt][nt+4][half*2+1];
                    if (region == 2) {
                        *(float2*)&dst[obase + i0]      = make_float2(a0, a1);
                        *(float2*)&dst[obase + i0 + 32] = make_float2(b0, b1);
                    } else {
                        const float2 cc = *(const float2*)&g_cos[t*32 + i0];
                        const float2 ss = *(const float2*)&g_sin[t*32 + i0];
                        float r10 = a0*cc.x - b0*ss.x, r20 = b0*cc.x + a0*ss.x;
                        float r11 = a1*cc.y - b1*ss.y, r21 = b1*cc.y + a1*ss.y;
                        if (region == 0) {
                            r10 *= 0.125f; r20 *= 0.125f; r11 *= 0.125f; r21 *= 0.125f;
                        }
                        *(float2*)&dst[obase + i0]      = make_float2(elu1(r10), elu1(r11));
                        *(float2*)&dst[obase + i0 + 32] = make_float2(elu1(r20), elu1(r21));
                    }
                }
            }
        }
    }
}

// ---------------------------------------------------------------------------
// merged prep: blocks [0, RX_BLOCKS) do round_x; the rest do RoPE tables
// ---------------------------------------------------------------------------
#define RX_BLOCKS (BT*D_/4/256)     // 16384
#define RT_BLOCKS (T_*32/256)       // 512

__global__ __launch_bounds__(256)
void prep_kernel(const float* __restrict__ x) {
    if (blockIdx.x < RX_BLOCKS) {
        int i = blockIdx.x * 256 + threadIdx.x;
        float4 v = ((const float4*)x)[i];
        v.x = tf32r(v.x); v.y = tf32r(v.y); v.z = tf32r(v.z); v.w = tf32r(v.w);
        ((float4*)g_xa)[i] = v;
    } else {
        int idx = (blockIdx.x - RX_BLOCKS) * 256 + threadIdx.x;
        int t = idx >> 5;
        int i = idx & 31;
        float inv = powf(500000.0f, -(float)i * (1.0f/32.0f));
        float a = (float)t * inv;
        g_cos[idx] = cosf(a);
        g_sin[idx] = sinf(a);
    }
}

// both weight transposes in ONE launch
__global__ __launch_bounds__(256)
void transpose_round_kernel(const float* __restrict__ wq, const float* __restrict__ wo) {
    __shared__ float tile[32][33];
    const int R = D_;
    const float* in; float* out; int Cc; int bx;
    if (blockIdx.x < NKV/32) { in = wq; out = g_wqT; Cc = NKV; bx = blockIdx.x * 32; }
    else                     { in = wo; out = g_woT; Cc = D_;  bx = (blockIdx.x - NKV/32) * 32; }
    int by = blockIdx.y * 32;
    int tx = threadIdx.x, ty = threadIdx.y;
    #pragma unroll
    for (int i = 0; i < 32; i += 8)
        tile[ty + i][tx] = in[(size_t)(by + ty + i) * Cc + bx + tx];
    __syncthreads();
    #pragma unroll
    for (int i = 0; i < 32; i += 8)
        out[(size_t)(bx + ty + i) * R + by + tx] = tf32r(tile[tx][ty + i]);
}

// ---------------------------------------------------------------------------
// kv partial accumulation: 128 threads, 8x4 register microtile, NCHUNK=32
// ---------------------------------------------------------------------------
__global__ __launch_bounds__(128)
void kv_accum_kernel() {
    int blk = blockIdx.x;
    int bh  = blk >> 5;
    int c   = blk & 31;
    int tid = threadIdx.x;
    int d0  = (tid >> 4) * 8;     // 0..56
    int j0  = (tid & 15) * 4;     // 0..60

    __shared__ float kb[16][64];
    __shared__ float vb[16][64];

    float acc[8][4] = {};
    float ks[8] = {};

    int t0 = c * CHLEN;
    for (int tb = 0; tb < CHLEN; tb += 16) {
        #pragma unroll
        for (int u = 0; u < 2; u++) {
            int f  = tid + u*128;
            int rr = f >> 4, c4 = f & 15;
            int t  = t0 + tb + rr;
            *(float4*)&kb[rr][c4*4] =
                *(const float4*)&g_kf[((size_t)bh*T_ + t)*HD + c4*4];
            *(float4*)&vb[rr][c4*4] =
                *(const float4*)&g_v[((size_t)bh*T_ + t)*HD + c4*4];
        }
        __syncthreads();
        #pragma unroll
        for (int tt = 0; tt < 16; tt++) {
            float kk[8], vv[4];
            *(float4*)&kk[0] = *(float4*)&kb[tt][d0];
            *(float4*)&kk[4] = *(float4*)&kb[tt][d0+4];
            *(float4*)&vv[0] = *(float4*)&vb[tt][j0];
            #pragma unroll
            for (int i = 0; i < 8; i++) {
                ks[i] += kk[i];
                #pragma unroll
                for (int j = 0; j < 4; j++)
                    acc[i][j] += kk[i] * vv[j];
            }
        }
        __syncthreads();
    }

    #pragma unroll
    for (int i = 0; i < 8; i++) {
        float* p = &g_kvp[((size_t)(c*BH + bh)*HD + d0 + i)*HD + j0];
        *(float4*)p = make_float4(acc[i][0], acc[i][1], acc[i][2], acc[i][3]);
    }
    if ((tid & 15) == 0) {
        #pragma unroll
        for (int i = 0; i < 8; i++)
            g_ksp[(c*BH + bh)*HD + d0 + i] = ks[i];
    }
}

// kv reduce: blocks [0, 1024) reduce g_kvp; blocks [1024, 1040) reduce g_ksp
__global__ void kv_reduce_kernel() {
    if (blockIdx.x < (BH*HD*HD)/256) {
        int idx = blockIdx.x * 256 + threadIdx.x;
        float s = 0.f;
        #pragma unroll
        for (int c = 0; c < NCHUNK; c++) s += g_kvp[(size_t)c*BH*HD*HD + idx];
        g_kv[idx] = s;
    } else {
        int idx = (blockIdx.x - (BH*HD*HD)/256) * 256 + threadIdx.x;
        if (idx < BH*HD) {
            float s = 0.f;
            #pragma unroll
            for (int c = 0; c < NCHUNK; c++) s += g_ksp[c*BH*HD + idx];
            g_ksum[idx] = s;
        }
    }
}

// ---------------------------------------------------------------------------
__global__ __launch_bounds__(256)
void attn_out_kernel() {
    int blk = blockIdx.x;
    int bh  = blk >> 6;
    int tc  = blk & 63;
    int b   = bh >> 4;
    int h   = bh & 15;
    int tid = threadIdx.x;

    __shared__ float skv[HD*HD];
    __shared__ float sks[HD];
    __shared__ float sqf[64*HD];

    #pragma unroll
    for (int u = 0; u < 16; u++) {
        int li = tid + u*256;
        skv[li] = g_kv[bh*HD*HD + li];
        sqf[li] = g_qf[((size_t)bh*T_ + tc*64)*HD + li];
    }
    if (tid < 64) sks[tid] = g_ksum[bh*HD + tid];
    __syncthreads();

    int tl = tid >> 2;
    int jb = (tid & 3) << 4;

    float den = 0.f;
    #pragma unroll
    for (int dd = 0; dd < 64; dd++) den += sqf[tl*64 + dd] * sks[dd];
    float sc = 1.f / fmaxf(den, 1e-6f);

    float4 acc[4] = {};
    #pragma unroll
    for (int dd = 0; dd < 64; dd++) {
        float qd = sqf[tl*64 + dd];
        const float4* kvr = (const float4*)&skv[dd*64 + jb];
        #pragma unroll
        for (int j4 = 0; j4 < 4; j4++) {
            float4 kk = kvr[j4];
            acc[j4].x += qd * kk.x;
            acc[j4].y += qd * kk.y;
            acc[j4].z += qd * kk.z;
            acc[j4].w += qd * kk.w;
        }
    }

    int t = tc*64 + tl;
    float* outp = &g_attn[((size_t)(b*T_ + t))*D_ + h*HD + jb];
    #pragma unroll
    for (int j4 = 0; j4 < 4; j4++) {
        float4 v = make_float4(tf32r(acc[j4].x*sc), tf32r(acc[j4].y*sc),
                               tf32r(acc[j4].z*sc), tf32r(acc[j4].w*sc));
        *(float4*)&outp[j4*4] = v;
    }
}

// ---------------------------------------------------------------------------
extern "C" void kernel_launch(void* const* d_in, const int* in_sizes, int n_in,
                              void* d_out, int out_size) {
    const float* x = nullptr; const float* Wqkv = nullptr; const float* Wout = nullptr;
    for (int i = 0; i < n_in; i++) {
        if (in_sizes[i] == BT*D_)       x    = (const float*)d_in[i];
        else if (in_sizes[i] == D_*NKV) Wqkv = (const float*)d_in[i];
        else if (in_sizes[i] == D_*D_)  Wout = (const float*)d_in[i];
    }
    float* out = (float*)d_out;

    float *attn_p, *xa_p, *wqT_p, *woT_p;
    cudaGetSymbolAddress((void**)&attn_p, g_attn);
    cudaGetSymbolAddress((void**)&xa_p,   g_xa);
    cudaGetSymbolAddress((void**)&wqT_p,  g_wqT);
    cudaGetSymbolAddress((void**)&woT_p,  g_woT);

    cudaFuncSetAttribute(gemm_tf32_kernel,
                         cudaFuncAttributeMaxDynamicSharedMemorySize, GEMM_SMEM);

    // launch 0: merged prep (tf32 round of x + fp32 RoPE tables)
    prep_kernel<<<RX_BLOCKS + RT_BLOCKS, 256>>>(x);
    // launch 1: weight transposes
    transpose_round_kernel<<<dim3(NKV/32 + D_/32, D_/32), dim3(32, 8)>>>(Wqkv, Wout);

    // launch 2: qkv GEMM with fused RoPE + feature-map epilogue
    gemm_tf32_kernel<<<dim3(NKV/128, BT/128), 256, GEMM_SMEM>>>(NKV, 1, xa_p, wqT_p, nullptr);

    // launch 3,4: kv & ksum
    kv_accum_kernel<<<BH*NCHUNK, 128>>>();
    kv_reduce_kernel<<<(BH*HD*HD)/256 + (BH*HD + 255)/256, 256>>>();

    // launch 5: attention epilogue
    attn_out_kernel<<<BH*64, 256>>>();

    // launch 6: out = attn @ W_out
    gemm_tf32_kernel<<<dim3(D_/128, BT/128), 256, GEMM_SMEM>>>(D_, 0, attn_p, woT_p, out);
}

// round 13
// speedup vs baseline: 1.8840x; 1.2062x over previous
#include <cuda_runtime.h>
#include <math.h>
#include <stdint.h>

// Problem constants
#define B_   4
#define T_   4096
#define D_   1024
#define H_   16
#define HD   64
#define BT   (B_*T_)      // 16384
#define BH   (B_*H_)      // 64
#define NKV  3072
#define NCHUNK 32
#define CHLEN (T_/NCHUNK) // 128
#define GK   1024

// Scratch
__device__ float g_qf [BH*T_*HD];
__device__ float g_kf [BH*T_*HD];
__device__ float g_v  [BH*T_*HD];
__device__ float g_kvp[NCHUNK*BH*HD*HD];
__device__ float g_kvT[BH*HD*HD];    // kv transposed [bh][j][d], tf32-rounded
__device__ float g_ksp[NCHUNK*BH*HD];
__device__ float g_ksum[BH*HD];
__device__ float g_attn[BT*D_];
__device__ float g_xa  [BT*D_];
__device__ float g_wqT [NKV*D_];
__device__ float g_woT [D_*D_];
__device__ float g_cos[T_*32];
__device__ float g_sin[T_*32];

// ---------------------------------------------------------------------------
__device__ __forceinline__ uint32_t smem_u32(const void* p) {
    uint32_t a;
    asm("{ .reg .u64 t; cvta.to.shared.u64 t, %1; cvt.u32.u64 %0, t; }"
        : "=r"(a) : "l"(p));
    return a;
}
__device__ __forceinline__ float tf32r(float x) {
    uint32_t o;
    asm("cvt.rna.tf32.f32 %0, %1;" : "=r"(o) : "f"(x));
    return __uint_as_float(o);
}
#define CP_ASYNC16(dst, src) \
    asm volatile("cp.async.cg.shared.global [%0], [%1], 16;" :: "r"(dst), "l"(src) : "memory")
#define CP_COMMIT()  asm volatile("cp.async.commit_group;" ::: "memory")
#define CP_WAIT2()   asm volatile("cp.async.wait_group 2;" ::: "memory")

__device__ __forceinline__ void ldsm_x4(uint32_t* r, uint32_t addr) {
    asm volatile("ldmatrix.sync.aligned.m8n8.x4.shared.b16 {%0,%1,%2,%3}, [%4];"
        : "=r"(r[0]), "=r"(r[1]), "=r"(r[2]), "=r"(r[3]) : "r"(addr));
}
__device__ __forceinline__ void mma_tf32(float* d, const uint32_t* a, const uint32_t* b) {
    asm volatile(
        "mma.sync.aligned.m16n8k8.row.col.f32.tf32.tf32.f32 "
        "{%0,%1,%2,%3}, {%4,%5,%6,%7}, {%8,%9}, {%0,%1,%2,%3};"
        : "+f"(d[0]), "+f"(d[1]), "+f"(d[2]), "+f"(d[3])
        : "r"(a[0]), "r"(a[1]), "r"(a[2]), "r"(a[3]),
          "r"(b[0]), "r"(b[1]));
}
__device__ __forceinline__ float elu1(float x) {
    return x > 0.f ? x + 1.f : expf(x);
}

// ---------------------------------------------------------------------------
// tf32 mma.sync GEMM (R6 config — best measured): 128x128 CTA tile, BK=16,
// 4-stage cp.async (wait_group 2) + barrier, 256 threads, warp tile 32x64,
// ldmatrix fragment loads, ROWF=20 padding (conflict-free).
// mode 0: plain C store. mode 1: fused RoPE/elu qkv epilogue (qf tf32-rounded).
// ---------------------------------------------------------------------------
#define STAGES 4
#define ROWF   20
#define STG_F  (128*ROWF)
#define GEMM_SMEM (2*STAGES*STG_F*4)    // 81920 B

__global__ __launch_bounds__(256, 2)
void gemm_tf32_kernel(int N, int mode, const float* __restrict__ A,
                      const float* __restrict__ Bt, float* __restrict__ C) {
    extern __shared__ float sm[];
    float* As = sm;
    float* Bs = sm + STAGES*STG_F;

    const int tid  = threadIdx.x;
    const int wid  = tid >> 5;
    const int lane = tid & 31;
    const int g    = lane >> 2;
    const int tg   = lane & 3;
    const int lrow = lane & 7;
    const int seg  = lane >> 3;      // 0..3

    const int rowBase = blockIdx.y * 128;
    const int colBase = blockIdx.x * 128;
    const int mBase = (wid & 3) * 32;
    const int nBase = (wid >> 2) * 64;

    // cp.async mapping: 2 threads per row, 8 floats (2x16B) each
    const int lr = tid >> 1;
    const int lc = (tid & 1) * 8;
    const float* aSrc = A  + (size_t)(rowBase + lr)*GK + lc;
    const float* bSrc = Bt + (size_t)(colBase + lr)*GK + lc;
    const uint32_t aDst = smem_u32(As) + (uint32_t)(lr*ROWF + lc)*4;
    const uint32_t bDst = smem_u32(Bs) + (uint32_t)(lr*ROWF + lc)*4;

    // ldmatrix per-lane base addresses
    const uint32_t aFrag0 = smem_u32(As) +
        (uint32_t)(((mBase + (seg & 1)*8 + lrow)*ROWF + (seg >> 1)*4) * 4);
    const uint32_t bFrag0 = smem_u32(Bs) +
        (uint32_t)(((nBase + (seg >> 1)*8 + lrow)*ROWF + (seg & 1)*4) * 4);

    float acc[2][8][4];
    #pragma unroll
    for (int mt = 0; mt < 2; mt++)
        #pragma unroll
        for (int nt = 0; nt < 8; nt++)
            #pragma unroll
            for (int q = 0; q < 4; q++) acc[mt][nt][q] = 0.f;

    // prologue: stages 0..2
    #pragma unroll
    for (int s = 0; s < STAGES-1; s++) {
        const uint32_t so = (uint32_t)s * (STG_F*4);
        const float* ap = aSrc + s*16;
        const float* bp = bSrc + s*16;
        CP_ASYNC16(aDst + so,      ap);
        CP_ASYNC16(aDst + so + 16, ap + 4);
        CP_ASYNC16(bDst + so,      bp);
        CP_ASYNC16(bDst + so + 16, bp + 4);
        CP_COMMIT();
    }

    const int NIT = GK / 16;   // 64
    for (int it = 0; it < NIT; it++) {
        CP_WAIT2();
        __syncthreads();

        const int nit = it + STAGES - 1;
        if (nit < NIT) {
            const int s = nit % STAGES;
            const uint32_t so = (uint32_t)s * (STG_F*4);
            const float* ap = aSrc + nit*16;
            const float* bp = bSrc + nit*16;
            CP_ASYNC16(aDst + so,      ap);
            CP_ASYNC16(aDst + so + 16, ap + 4);
            CP_ASYNC16(bDst + so,      bp);
            CP_ASYNC16(bDst + so + 16, bp + 4);
        }
        CP_COMMIT();

        const uint32_t so = (uint32_t)(it % STAGES) * (STG_F*4);
        const uint32_t aF = aFrag0 + so;
        const uint32_t bF = bFrag0 + so;
        #pragma unroll
        for (int ks = 0; ks < 16; ks += 8) {
            uint32_t af[2][4];
            uint32_t bf[4][4];   // pair p covers n-tiles 2p, 2p+1
            ldsm_x4(af[0], aF             + ks*4);
            ldsm_x4(af[1], aF + 16*ROWF*4 + ks*4);
            #pragma unroll
            for (int p = 0; p < 4; p++)
                ldsm_x4(bf[p], bF + p*16*ROWF*4 + ks*4);
            #pragma unroll
            for (int mt = 0; mt < 2; mt++)
                #pragma unroll
                for (int nt = 0; nt < 8; nt++)
                    mma_tf32(acc[mt][nt], af[mt], &bf[nt >> 1][(nt & 1)*2]);
        }
    }

    if (mode == 0) {
        #pragma unroll
        for (int mt = 0; mt < 2; mt++) {
            const int r0 = rowBase + mBase + mt*16 + g;
            #pragma unroll
            for (int nt = 0; nt < 8; nt++) {
                const int c0 = colBase + nBase + nt*8 + tg*2;
                *(float2*)&C[(size_t) r0   *N + c0] = make_float2(acc[mt][nt][0], acc[mt][nt][1]);
                *(float2*)&C[(size_t)(r0+8)*N + c0] = make_float2(acc[mt][nt][2], acc[mt][nt][3]);
            }
        }
    } else {
        // fused qkv epilogue. Warp's 64 cols = one head of q, k, or v.
        const int region = colBase >> 10;            // 0=q 1=k 2=v
        float* dst = (region == 0) ? g_qf : (region == 1 ? g_kf : g_v);
        const int head = (((colBase & 1023) + nBase) >> 6);
        #pragma unroll
        for (int mt = 0; mt < 2; mt++) {
            #pragma unroll
            for (int half = 0; half < 2; half++) {
                const int row = rowBase + mBase + mt*16 + g + half*8;
                const int t = row & (T_-1);
                const int b = row >> 12;
                const size_t obase = ((size_t)(b*H_ + head)*T_ + t)*HD;
                #pragma unroll
                for (int nt = 0; nt < 4; nt++) {
                    const int i0 = nt*8 + tg*2;
                    const float a0 = acc[mt][nt  ][half*2+0];
                    const float a1 = acc[mt][nt  ][half*2+1];
                    const float b0 = acc[mt][nt+4][half*2+0];
                    const float b1 = acc[mt][nt+4][half*2+1];
                    if (region == 2) {
                        *(float2*)&dst[obase + i0]      = make_float2(a0, a1);
                        *(float2*)&dst[obase + i0 + 32] = make_float2(b0, b1);
                    } else {
                        const float2 cc = *(const float2*)&g_cos[t*32 + i0];
                        const float2 ss = *(const float2*)&g_sin[t*32 + i0];
                        float r10 = a0*cc.x - b0*ss.x, r20 = b0*cc.x + a0*ss.x;
                        float r11 = a1*cc.y - b1*ss.y, r21 = b1*cc.y + a1*ss.y;
                        if (region == 0) {
                            r10 *= 0.125f; r20 *= 0.125f; r11 *= 0.125f; r21 *= 0.125f;
                            // qf is consumed by the tf32 attn MMA: round at storage
                            *(float2*)&dst[obase + i0]      =
                                make_float2(tf32r(elu1(r10)), tf32r(elu1(r11)));
                            *(float2*)&dst[obase + i0 + 32] =
                                make_float2(tf32r(elu1(r20)), tf32r(elu1(r21)));
                        } else {
                            *(float2*)&dst[obase + i0]      = make_float2(elu1(r10), elu1(r11));
                            *(float2*)&dst[obase + i0 + 32] = make_float2(elu1(r20), elu1(r21));
                        }
                    }
                }
            }
        }
    }
}

// ---------------------------------------------------------------------------
// merged prep: blocks [0, RX_BLOCKS) do round_x; the rest do RoPE tables
// ---------------------------------------------------------------------------
#define RX_BLOCKS (BT*D_/4/256)     // 16384
#define RT_BLOCKS (T_*32/256)       // 512

__global__ __launch_bounds__(256)
void prep_kernel(const float* __restrict__ x) {
    if (blockIdx.x < RX_BLOCKS) {
        int i = blockIdx.x * 256 + threadIdx.x;
        float4 v = ((const float4*)x)[i];
        v.x = tf32r(v.x); v.y = tf32r(v.y); v.z = tf32r(v.z); v.w = tf32r(v.w);
        ((float4*)g_xa)[i] = v;
    } else {
        int idx = (blockIdx.x - RX_BLOCKS) * 256 + threadIdx.x;
        int t = idx >> 5;
        int i = idx & 31;
        float inv = powf(500000.0f, -(float)i * (1.0f/32.0f));
        float a = (float)t * inv;
        g_cos[idx] = cosf(a);
        g_sin[idx] = sinf(a);
    }
}

// both weight transposes in ONE launch
__global__ __launch_bounds__(256)
void transpose_round_kernel(const float* __restrict__ wq, const float* __restrict__ wo) {
    __shared__ float tile[32][33];
    const int R = D_;
    const float* in; float* out; int Cc; int bx;
    if (blockIdx.x < NKV/32) { in = wq; out = g_wqT; Cc = NKV; bx = blockIdx.x * 32; }
    else                     { in = wo; out = g_woT; Cc = D_;  bx = (blockIdx.x - NKV/32) * 32; }
    int by = blockIdx.y * 32;
    int tx = threadIdx.x, ty = threadIdx.y;
    #pragma unroll
    for (int i = 0; i < 32; i += 8)
        tile[ty + i][tx] = in[(size_t)(by + ty + i) * Cc + bx + tx];
    __syncthreads();
    #pragma unroll
    for (int i = 0; i < 32; i += 8)
        out[(size_t)(bx + ty + i) * R + by + tx] = tf32r(tile[tx][ty + i]);
}

// ---------------------------------------------------------------------------
// kv partial accumulation: 128 threads, 8x4 register microtile, NCHUNK=32
// ---------------------------------------------------------------------------
__global__ __launch_bounds__(128)
void kv_accum_kernel() {
    int blk = blockIdx.x;
    int bh  = blk >> 5;
    int c   = blk & 31;
    int tid = threadIdx.x;
    int d0  = (tid >> 4) * 8;     // 0..56
    int j0  = (tid & 15) * 4;     // 0..60

    __shared__ float kb[16][64];
    __shared__ float vb[16][64];

    float acc[8][4] = {};
    float ks[8] = {};

    int t0 = c * CHLEN;
    for (int tb = 0; tb < CHLEN; tb += 16) {
        #pragma unroll
        for (int u = 0; u < 2; u++) {
            int f  = tid + u*128;
            int rr = f >> 4, c4 = f & 15;
            int t  = t0 + tb + rr;
            *(float4*)&kb[rr][c4*4] =
                *(const float4*)&g_kf[((size_t)bh*T_ + t)*HD + c4*4];
            *(float4*)&vb[rr][c4*4] =
                *(const float4*)&g_v[((size_t)bh*T_ + t)*HD + c4*4];
        }
        __syncthreads();
        #pragma unroll
        for (int tt = 0; tt < 16; tt++) {
            float kk[8], vv[4];
            *(float4*)&kk[0] = *(float4*)&kb[tt][d0];
            *(float4*)&kk[4] = *(float4*)&kb[tt][d0+4];
            *(float4*)&vv[0] = *(float4*)&vb[tt][j0];
            #pragma unroll
            for (int i = 0; i < 8; i++) {
                ks[i] += kk[i];
                #pragma unroll
                for (int j = 0; j < 4; j++)
                    acc[i][j] += kk[i] * vv[j];
            }
        }
        __syncthreads();
    }

    #pragma unroll
    for (int i = 0; i < 8; i++) {
        float* p = &g_kvp[((size_t)(c*BH + bh)*HD + d0 + i)*HD + j0];
        *(float4*)p = make_float4(acc[i][0], acc[i][1], acc[i][2], acc[i][3]);
    }
    if ((tid & 15) == 0) {
        #pragma unroll
        for (int i = 0; i < 8; i++)
            g_ksp[(c*BH + bh)*HD + d0 + i] = ks[i];
    }
}

// kv reduce: blocks [0, 1024) reduce g_kvp -> g_kvT (transposed, tf32-rounded);
// blocks [1024, 1040) reduce g_ksp -> g_ksum.
__global__ void kv_reduce_kernel() {
    if (blockIdx.x < (BH*HD*HD)/256) {
        int idx = blockIdx.x * 256 + threadIdx.x;
        float s = 0.f;
        #pragma unroll
        for (int c = 0; c < NCHUNK; c++) s += g_kvp[(size_t)c*BH*HD*HD + idx];
        int j  = idx & 63;
        int d  = (idx >> 6) & 63;
        int bh = idx >> 12;
        g_kvT[bh*HD*HD + j*HD + d] = tf32r(s);
    } else {
        int idx = (blockIdx.x - (BH*HD*HD)/256) * 256 + threadIdx.x;
        if (idx < BH*HD) {
            float s = 0.f;
            #pragma unroll
            for (int c = 0; c < NCHUNK; c++) s += g_ksp[c*BH*HD + idx];
            g_ksum[idx] = s;
        }
    }
}

// ---------------------------------------------------------------------------
// attn numerator via tf32 MMA: per block (bh, 128 t-rows): out[t][j] =
// (qf[t,:] @ kvT[j,:]) * 1/max(qf[t,:].ksum, 1e-6). 128 threads = 4 warps of
// 32(m)x64(n) tiles, K=64 in 8 k8 steps. Same ldmatrix addressing scheme as
// the main GEMM (ROWQ = 68 floats/row: 68 mod 8 == 4, same conflict-free class
// as ROWF=20). Denominator computed scalar fp32 (1/65 of the FLOP).
// ---------------------------------------------------------------------------
#define ROWQ 68
#define ATT_SMEM ((192*ROWQ + 64 + 128)*4)   // qa + kvb + sks + sden

__global__ __launch_bounds__(128)
void attn_mma_kernel() {
    extern __shared__ float sm[];
    float* qa  = sm;                  // [128][ROWQ]
    float* kvb = sm + 128*ROWQ;       // [64][ROWQ]
    float* sks = sm + 192*ROWQ;       // [64]
    float* sden= sks + 64;            // [128]

    const int blk = blockIdx.x;
    const int bh  = blk >> 5;
    const int tc  = blk & 31;
    const int b   = bh >> 4;
    const int h   = bh & 15;
    const int tid = threadIdx.x;
    const int wid = tid >> 5;
    const int lane = tid & 31;
    const int g    = lane >> 2;
    const int tg   = lane & 3;
    const int lrow = lane & 7;
    const int seg  = lane >> 3;

    // fill qa (128 rows x 64) and kvb (64 rows x 64), coalesced
    #pragma unroll
    for (int u = 0; u < 16; u++) {
        int f  = tid + u*128;          // 0..2047
        int rr = f >> 4, c4 = f & 15;
        *(float4*)&qa[rr*ROWQ + c4*4] =
            *(const float4*)&g_qf[((size_t)bh*T_ + tc*128 + rr)*HD + c4*4];
    }
    #pragma unroll
    for (int u = 0; u < 8; u++) {
        int f  = tid + u*128;          // 0..1023
        int rr = f >> 4, c4 = f & 15;
        *(float4*)&kvb[rr*ROWQ + c4*4] =
            *(const float4*)&g_kvT[bh*HD*HD + rr*HD + c4*4];
    }
    if (tid < 64) sks[tid] = g_ksum[bh*HD + tid];
    __syncthreads();

    // denominator: thread tid owns row tid (conflict-free: 17*tid mod 32 distinct)
    {
        float den = 0.f;
        #pragma unroll
        for (int d = 0; d < 64; d++) den += qa[tid*ROWQ + d] * sks[d];
        sden[tid] = 1.f / fmaxf(den, 1e-6f);
    }
    __syncthreads();

    // MMA: warp tile 32x64
    const int mBase = wid * 32;
    const uint32_t aFrag0 = smem_u32(qa) +
        (uint32_t)(((mBase + (seg & 1)*8 + lrow)*ROWQ + (seg >> 1)*4) * 4);
    const uint32_t bFrag0 = smem_u32(kvb) +
        (uint32_t)((((seg >> 1)*8 + lrow)*ROWQ + (seg & 1)*4) * 4);

    float acc[2][8][4];
    #pragma unroll
    for (int mt = 0; mt < 2; mt++)
        #pragma unroll
        for (int nt = 0; nt < 8; nt++)
            #pragma unroll
            for (int q = 0; q < 4; q++) acc[mt][nt][q] = 0.f;

    #pragma unroll
    for (int ks = 0; ks < 64; ks += 8) {
        uint32_t af[2][4];
        uint32_t bf[4][4];
        ldsm_x4(af[0], aFrag0             + ks*4);
        ldsm_x4(af[1], aFrag0 + 16*ROWQ*4 + ks*4);
        #pragma unroll
        for (int p = 0; p < 4; p++)
            ldsm_x4(bf[p], bFrag0 + p*16*ROWQ*4 + ks*4);
        #pragma unroll
        for (int mt = 0; mt < 2; mt++)
            #pragma unroll
            for (int nt = 0; nt < 8; nt++)
                mma_tf32(acc[mt][nt], af[mt], &bf[nt >> 1][(nt & 1)*2]);
    }

    // epilogue: scale by 1/den, tf32-round (feeds GEMM2), store to g_attn
    #pragma unroll
    for (int mt = 0; mt < 2; mt++) {
        const int rl0 = mBase + mt*16 + g;
        const float s0 = sden[rl0];
        const float s1 = sden[rl0 + 8];
        const int t0 = tc*128 + rl0;
        float* o0 = &g_attn[((size_t)(b*T_ + t0    ))*D_ + h*HD];
        float* o1 = &g_attn[((size_t)(b*T_ + t0 + 8))*D_ + h*HD];
        #pragma unroll
        for (int nt = 0; nt < 8; nt++) {
            const int c0 = nt*8 + tg*2;
            *(float2*)&o0[c0] = make_float2(tf32r(acc[mt][nt][0]*s0), tf32r(acc[mt][nt][1]*s0));
            *(float2*)&o1[c0] = make_float2(tf32r(acc[mt][nt][2]*s1), tf32r(acc[mt][nt][3]*s1));
        }
    }
}

// ---------------------------------------------------------------------------
extern "C" void kernel_launch(void* const* d_in, const int* in_sizes, int n_in,
                              void* d_out, int out_size) {
    const float* x = nullptr; const float* Wqkv = nullptr; const float* Wout = nullptr;
    for (int i = 0; i < n_in; i++) {
        if (in_sizes[i] == BT*D_)       x    = (const float*)d_in[i];
        else if (in_sizes[i] == D_*NKV) Wqkv = (const float*)d_in[i];
        else if (in_sizes[i] == D_*D_)  Wout = (const float*)d_in[i];
    }
    float* out = (float*)d_out;

    float *attn_p, *xa_p, *wqT_p, *woT_p;
    cudaGetSymbolAddress((void**)&attn_p, g_attn);
    cudaGetSymbolAddress((void**)&xa_p,   g_xa);
    cudaGetSymbolAddress((void**)&wqT_p,  g_wqT);
    cudaGetSymbolAddress((void**)&woT_p,  g_woT);

    cudaFuncSetAttribute(gemm_tf32_kernel,
                         cudaFuncAttributeMaxDynamicSharedMemorySize, GEMM_SMEM);
    cudaFuncSetAttribute(attn_mma_kernel,
                         cudaFuncAttributeMaxDynamicSharedMemorySize, ATT_SMEM);

    // launch 0: merged prep (tf32 round of x + fp32 RoPE tables)
    prep_kernel<<<RX_BLOCKS + RT_BLOCKS, 256>>>(x);
    // launch 1: weight transposes
    transpose_round_kernel<<<dim3(NKV/32 + D_/32, D_/32), dim3(32, 8)>>>(Wqkv, Wout);

    // launch 2: qkv GEMM with fused RoPE + feature-map epilogue
    gemm_tf32_kernel<<<dim3(NKV/128, BT/128), 256, GEMM_SMEM>>>(NKV, 1, xa_p, wqT_p, nullptr);

    // launch 3,4: kv & ksum (reduce emits transposed tf32 kvT)
    kv_accum_kernel<<<BH*NCHUNK, 128>>>();
    kv_reduce_kernel<<<(BH*HD*HD)/256 + (BH*HD + 255)/256, 256>>>();

    // launch 5: attention epilogue via tf32 MMA
    attn_mma_kernel<<<BH*32, 128, ATT_SMEM>>>();

    // launch 6: out = attn @ W_out
    gemm_tf32_kernel<<<dim3(D_/128, BT/128), 256, GEMM_SMEM>>>(D_, 0, attn_p, woT_p, out);
}

// round 14
// speedup vs baseline: 1.9107x; 1.0141x over previous
#include <cuda_runtime.h>
#include <math.h>
#include <stdint.h>

// Problem constants
#define B_   4
#define T_   4096
#define D_   1024
#define H_   16
#define HD   64
#define BT   (B_*T_)      // 16384
#define BH   (B_*H_)      // 64
#define NKV  3072
#define NCHUNK 32
#define CHLEN (T_/NCHUNK) // 128
#define GK   1024

// Scratch
__device__ float g_qf [BH*T_*HD];
__device__ float g_kf [BH*T_*HD];
__device__ float g_v  [BH*T_*HD];
__device__ float g_kvp[NCHUNK*BH*HD*HD];
__device__ float g_kvT[BH*HD*HD];    // kv transposed [bh][j][d], tf32-rounded
__device__ float g_ksp[NCHUNK*BH*HD];
__device__ float g_ksum[BH*HD];
__device__ float g_attn[BT*D_];
__device__ float g_xa  [BT*D_];
__device__ float g_wqT [NKV*D_];
__device__ float g_woT [D_*D_];
__device__ float g_cos[T_*32];
__device__ float g_sin[T_*32];

// ---------------------------------------------------------------------------
__device__ __forceinline__ uint32_t smem_u32(const void* p) {
    uint32_t a;
    asm("{ .reg .u64 t; cvta.to.shared.u64 t, %1; cvt.u32.u64 %0, t; }"
        : "=r"(a) : "l"(p));
    return a;
}
__device__ __forceinline__ float tf32r(float x) {
    uint32_t o;
    asm("cvt.rna.tf32.f32 %0, %1;" : "=r"(o) : "f"(x));
    return __uint_as_float(o);
}
#define CP_ASYNC16(dst, src) \
    asm volatile("cp.async.cg.shared.global [%0], [%1], 16;" :: "r"(dst), "l"(src) : "memory")
#define CP_COMMIT()  asm volatile("cp.async.commit_group;" ::: "memory")
#define CP_WAIT2()   asm volatile("cp.async.wait_group 2;" ::: "memory")

__device__ __forceinline__ void ldsm_x4(uint32_t* r, uint32_t addr) {
    asm volatile("ldmatrix.sync.aligned.m8n8.x4.shared.b16 {%0,%1,%2,%3}, [%4];"
        : "=r"(r[0]), "=r"(r[1]), "=r"(r[2]), "=r"(r[3]) : "r"(addr));
}
__device__ __forceinline__ void mma_tf32(float* d, const uint32_t* a, const uint32_t* b) {
    asm volatile(
        "mma.sync.aligned.m16n8k8.row.col.f32.tf32.tf32.f32 "
        "{%0,%1,%2,%3}, {%4,%5,%6,%7}, {%8,%9}, {%0,%1,%2,%3};"
        : "+f"(d[0]), "+f"(d[1]), "+f"(d[2]), "+f"(d[3])
        : "r"(a[0]), "r"(a[1]), "r"(a[2]), "r"(a[3]),
          "r"(b[0]), "r"(b[1]));
}
__device__ __forceinline__ float elu1(float x) {
    return x > 0.f ? x + 1.f : expf(x);
}

// ---------------------------------------------------------------------------
// tf32 mma.sync GEMM: 128x128 CTA tile, BK=16, 4-stage cp.async (wait_group 2)
// + barrier, 256 threads, warp tile 32x64, ldmatrix fragments, ROWF=20.
// ANTI-PHASE: odd warps process the ks=8 half-step first, even warps ks=0
// first — at any instant half the resident warps are in the LDSM (LSU) phase
// while the other half are in the MMA (tensor) phase, breaking the 50% duty
// cycle caused by barrier-aligned identical asm schedules.
// mode 0: plain C store. mode 1: fused RoPE/elu qkv epilogue (qf tf32-rounded).
// ---------------------------------------------------------------------------
#define STAGES 4
#define ROWF   20
#define STG_F  (128*ROWF)
#define GEMM_SMEM (2*STAGES*STG_F*4)    // 81920 B

__global__ __launch_bounds__(256, 2)
void gemm_tf32_kernel(int N, int mode, const float* __restrict__ A,
                      const float* __restrict__ Bt, float* __restrict__ C) {
    extern __shared__ float sm[];
    float* As = sm;
    float* Bs = sm + STAGES*STG_F;

    const int tid  = threadIdx.x;
    const int wid  = tid >> 5;
    const int lane = tid & 31;
    const int g    = lane >> 2;
    const int tg   = lane & 3;
    const int lrow = lane & 7;
    const int seg  = lane >> 3;      // 0..3

    const int rowBase = blockIdx.y * 128;
    const int colBase = blockIdx.x * 128;
    const int mBase = (wid & 3) * 32;
    const int nBase = (wid >> 2) * 64;

    // cp.async mapping: 2 threads per row, 8 floats (2x16B) each
    const int lr = tid >> 1;
    const int lc = (tid & 1) * 8;
    const float* aSrc = A  + (size_t)(rowBase + lr)*GK + lc;
    const float* bSrc = Bt + (size_t)(colBase + lr)*GK + lc;
    const uint32_t aDst = smem_u32(As) + (uint32_t)(lr*ROWF + lc)*4;
    const uint32_t bDst = smem_u32(Bs) + (uint32_t)(lr*ROWF + lc)*4;

    // ldmatrix per-lane base addresses
    const uint32_t aFrag0 = smem_u32(As) +
        (uint32_t)(((mBase + (seg & 1)*8 + lrow)*ROWF + (seg >> 1)*4) * 4);
    const uint32_t bFrag0 = smem_u32(Bs) +
        (uint32_t)(((nBase + (seg >> 1)*8 + lrow)*ROWF + (seg & 1)*4) * 4);

    // anti-phase ks byte offsets (ks=8 <-> 32 bytes)
    const uint32_t ksA = (wid & 1) ? 32u : 0u;
    const uint32_t ksB = ksA ^ 32u;

    float acc[2][8][4];
    #pragma unroll
    for (int mt = 0; mt < 2; mt++)
        #pragma unroll
        for (int nt = 0; nt < 8; nt++)
            #pragma unroll
            for (int q = 0; q < 4; q++) acc[mt][nt][q] = 0.f;

    // prologue: stages 0..2
    #pragma unroll
    for (int s = 0; s < STAGES-1; s++) {
        const uint32_t so = (uint32_t)s * (STG_F*4);
        const float* ap = aSrc + s*16;
        const float* bp = bSrc + s*16;
        CP_ASYNC16(aDst + so,      ap);
        CP_ASYNC16(aDst + so + 16, ap + 4);
        CP_ASYNC16(bDst + so,      bp);
        CP_ASYNC16(bDst + so + 16, bp + 4);
        CP_COMMIT();
    }

    const int NIT = GK / 16;   // 64
    for (int it = 0; it < NIT; it++) {
        CP_WAIT2();
        __syncthreads();

        const int nit = it + STAGES - 1;
        if (nit < NIT) {
            const int s = nit % STAGES;
            const uint32_t so = (uint32_t)s * (STG_F*4);
            const float* ap = aSrc + nit*16;
            const float* bp = bSrc + nit*16;
            CP_ASYNC16(aDst + so,      ap);
            CP_ASYNC16(aDst + so + 16, ap + 4);
            CP_ASYNC16(bDst + so,      bp);
            CP_ASYNC16(bDst + so + 16, bp + 4);
        }
        CP_COMMIT();

        const uint32_t so = (uint32_t)(it % STAGES) * (STG_F*4);
        const uint32_t aF = aFrag0 + so;
        const uint32_t bF = bFrag0 + so;
        // phase 1: this warp's first half-step (ksA)
        {
            uint32_t af[2][4], bf[4][4];
            ldsm_x4(af[0], aF             + ksA);
            ldsm_x4(af[1], aF + 16*ROWF*4 + ksA);
            #pragma unroll
            for (int p = 0; p < 4; p++)
                ldsm_x4(bf[p], bF + p*16*ROWF*4 + ksA);
            #pragma unroll
            for (int mt = 0; mt < 2; mt++)
                #pragma unroll
                for (int nt = 0; nt < 8; nt++)
                    mma_tf32(acc[mt][nt], af[mt], &bf[nt >> 1][(nt & 1)*2]);
        }
        // phase 2: the other half-step (ksB)
        {
            uint32_t af[2][4], bf[4][4];
            ldsm_x4(af[0], aF             + ksB);
            ldsm_x4(af[1], aF + 16*ROWF*4 + ksB);
            #pragma unroll
            for (int p = 0; p < 4; p++)
                ldsm_x4(bf[p], bF + p*16*ROWF*4 + ksB);
            #pragma unroll
            for (int mt = 0; mt < 2; mt++)
                #pragma unroll
                for (int nt = 0; nt < 8; nt++)
                    mma_tf32(acc[mt][nt], af[mt], &bf[nt >> 1][(nt & 1)*2]);
        }
    }

    if (mode == 0) {
        #pragma unroll
        for (int mt = 0; mt < 2; mt++) {
            const int r0 = rowBase + mBase + mt*16 + g;
            #pragma unroll
            for (int nt = 0; nt < 8; nt++) {
                const int c0 = colBase + nBase + nt*8 + tg*2;
                *(float2*)&C[(size_t) r0   *N + c0] = make_float2(acc[mt][nt][0], acc[mt][nt][1]);
                *(float2*)&C[(size_t)(r0+8)*N + c0] = make_float2(acc[mt][nt][2], acc[mt][nt][3]);
            }
        }
    } else {
        // fused qkv epilogue. Warp's 64 cols = one head of q, k, or v.
        const int region = colBase >> 10;            // 0=q 1=k 2=v
        float* dst = (region == 0) ? g_qf : (region == 1 ? g_kf : g_v);
        const int head = (((colBase & 1023) + nBase) >> 6);
        #pragma unroll
        for (int mt = 0; mt < 2; mt++) {
            #pragma unroll
            for (int half = 0; half < 2; half++) {
                const int row = rowBase + mBase + mt*16 + g + half*8;
                const int t = row & (T_-1);
                const int b = row >> 12;
                const size_t obase = ((size_t)(b*H_ + head)*T_ + t)*HD;
                #pragma unroll
                for (int nt = 0; nt < 4; nt++) {
                    const int i0 = nt*8 + tg*2;
                    const float a0 = acc[mt][nt  ][half*2+0];
                    const float a1 = acc[mt][nt  ][half*2+1];
                    const float b0 = acc[mt][nt+4][half*2+0];
                    const float b1 = acc[mt][nt+4][half*2+1];
                    if (region == 2) {
                        *(float2*)&dst[obase + i0]      = make_float2(a0, a1);
                        *(float2*)&dst[obase + i0 + 32] = make_float2(b0, b1);
                    } else {
                        const float2 cc = *(const float2*)&g_cos[t*32 + i0];
                        const float2 ss = *(const float2*)&g_sin[t*32 + i0];
                        float r10 = a0*cc.x - b0*ss.x, r20 = b0*cc.x + a0*ss.x;
                        float r11 = a1*cc.y - b1*ss.y, r21 = b1*cc.y + a1*ss.y;
                        if (region == 0) {
                            r10 *= 0.125f; r20 *= 0.125f; r11 *= 0.125f; r21 *= 0.125f;
                            *(float2*)&dst[obase + i0]      =
                                make_float2(tf32r(elu1(r10)), tf32r(elu1(r11)));
                            *(float2*)&dst[obase + i0 + 32] =
                                make_float2(tf32r(elu1(r20)), tf32r(elu1(r21)));
                        } else {
                            *(float2*)&dst[obase + i0]      = make_float2(elu1(r10), elu1(r11));
                            *(float2*)&dst[obase + i0 + 32] = make_float2(elu1(r20), elu1(r21));
                        }
                    }
                }
            }
        }
    }
}

// ---------------------------------------------------------------------------
// merged prep: blocks [0, RX_BLOCKS) do round_x; the rest do RoPE tables
// ---------------------------------------------------------------------------
#define RX_BLOCKS (BT*D_/4/256)     // 16384
#define RT_BLOCKS (T_*32/256)       // 512

__global__ __launch_bounds__(256)
void prep_kernel(const float* __restrict__ x) {
    if (blockIdx.x < RX_BLOCKS) {
        int i = blockIdx.x * 256 + threadIdx.x;
        float4 v = ((const float4*)x)[i];
        v.x = tf32r(v.x); v.y = tf32r(v.y); v.z = tf32r(v.z); v.w = tf32r(v.w);
        ((float4*)g_xa)[i] = v;
    } else {
        int idx = (blockIdx.x - RX_BLOCKS) * 256 + threadIdx.x;
        int t = idx >> 5;
        int i = idx & 31;
        float inv = powf(500000.0f, -(float)i * (1.0f/32.0f));
        float a = (float)t * inv;
        g_cos[idx] = cosf(a);
        g_sin[idx] = sinf(a);
    }
}

// both weight transposes in ONE launch
__global__ __launch_bounds__(256)
void transpose_round_kernel(const float* __restrict__ wq, const float* __restrict__ wo) {
    __shared__ float tile[32][33];
    const int R = D_;
    const float* in; float* out; int Cc; int bx;
    if (blockIdx.x < NKV/32) { in = wq; out = g_wqT; Cc = NKV; bx = blockIdx.x * 32; }
    else                     { in = wo; out = g_woT; Cc = D_;  bx = (blockIdx.x - NKV/32) * 32; }
    int by = blockIdx.y * 32;
    int tx = threadIdx.x, ty = threadIdx.y;
    #pragma unroll
    for (int i = 0; i < 32; i += 8)
        tile[ty + i][tx] = in[(size_t)(by + ty + i) * Cc + bx + tx];
    __syncthreads();
    #pragma unroll
    for (int i = 0; i < 32; i += 8)
        out[(size_t)(bx + ty + i) * R + by + tx] = tf32r(tile[tx][ty + i]);
}

// ---------------------------------------------------------------------------
// kv partial accumulation: 128 threads, 8x4 register microtile, NCHUNK=32
// ---------------------------------------------------------------------------
__global__ __launch_bounds__(128)
void kv_accum_kernel() {
    int blk = blockIdx.x;
    int bh  = blk >> 5;
    int c   = blk & 31;
    int tid = threadIdx.x;
    int d0  = (tid >> 4) * 8;     // 0..56
    int j0  = (tid & 15) * 4;     // 0..60

    __shared__ float kb[16][64];
    __shared__ float vb[16][64];

    float acc[8][4] = {};
    float ks[8] = {};

    int t0 = c * CHLEN;
    for (int tb = 0; tb < CHLEN; tb += 16) {
        #pragma unroll
        for (int u = 0; u < 2; u++) {
            int f  = tid + u*128;
            int rr = f >> 4, c4 = f & 15;
            int t  = t0 + tb + rr;
            *(float4*)&kb[rr][c4*4] =
                *(const float4*)&g_kf[((size_t)bh*T_ + t)*HD + c4*4];
            *(float4*)&vb[rr][c4*4] =
                *(const float4*)&g_v[((size_t)bh*T_ + t)*HD + c4*4];
        }
        __syncthreads();
        #pragma unroll
        for (int tt = 0; tt < 16; tt++) {
            float kk[8], vv[4];
            *(float4*)&kk[0] = *(float4*)&kb[tt][d0];
            *(float4*)&kk[4] = *(float4*)&kb[tt][d0+4];
            *(float4*)&vv[0] = *(float4*)&vb[tt][j0];
            #pragma unroll
            for (int i = 0; i < 8; i++) {
                ks[i] += kk[i];
                #pragma unroll
                for (int j = 0; j < 4; j++)
                    acc[i][j] += kk[i] * vv[j];
            }
        }
        __syncthreads();
    }

    #pragma unroll
    for (int i = 0; i < 8; i++) {
        float* p = &g_kvp[((size_t)(c*BH + bh)*HD + d0 + i)*HD + j0];
        *(float4*)p = make_float4(acc[i][0], acc[i][1], acc[i][2], acc[i][3]);
    }
    if ((tid & 15) == 0) {
        #pragma unroll
        for (int i = 0; i < 8; i++)
            g_ksp[(c*BH + bh)*HD + d0 + i] = ks[i];
    }
}

// kv reduce: blocks [0, 1024) reduce g_kvp -> g_kvT (transposed, tf32-rounded);
// blocks [1024, 1040) reduce g_ksp -> g_ksum.
__global__ void kv_reduce_kernel() {
    if (blockIdx.x < (BH*HD*HD)/256) {
        int idx = blockIdx.x * 256 + threadIdx.x;
        float s = 0.f;
        #pragma unroll
        for (int c = 0; c < NCHUNK; c++) s += g_kvp[(size_t)c*BH*HD*HD + idx];
        int j  = idx & 63;
        int d  = (idx >> 6) & 63;
        int bh = idx >> 12;
        g_kvT[bh*HD*HD + j*HD + d] = tf32r(s);
    } else {
        int idx = (blockIdx.x - (BH*HD*HD)/256) * 256 + threadIdx.x;
        if (idx < BH*HD) {
            float s = 0.f;
            #pragma unroll
            for (int c = 0; c < NCHUNK; c++) s += g_ksp[c*BH*HD + idx];
            g_ksum[idx] = s;
        }
    }
}

// ---------------------------------------------------------------------------
// attn numerator via tf32 MMA (R13 config, + anti-phase ks rotation).
// ---------------------------------------------------------------------------
#define ROWQ 68
#define ATT_SMEM ((192*ROWQ + 64 + 128)*4)   // qa + kvb + sks + sden

__global__ __launch_bounds__(128)
void attn_mma_kernel() {
    extern __shared__ float sm[];
    float* qa  = sm;                  // [128][ROWQ]
    float* kvb = sm + 128*ROWQ;       // [64][ROWQ]
    float* sks = sm + 192*ROWQ;       // [64]
    float* sden= sks + 64;            // [128]

    const int blk = blockIdx.x;
    const int bh  = blk >> 5;
    const int tc  = blk & 31;
    const int b   = bh >> 4;
    const int h   = bh & 15;
    const int tid = threadIdx.x;
    const int wid = tid >> 5;
    const int lane = tid & 31;
    const int g    = lane >> 2;
    const int tg   = lane & 3;
    const int lrow = lane & 7;
    const int seg  = lane >> 3;

    // fill qa (128 rows x 64) and kvb (64 rows x 64), coalesced
    #pragma unroll
    for (int u = 0; u < 16; u++) {
        int f  = tid + u*128;
        int rr = f >> 4, c4 = f & 15;
        *(float4*)&qa[rr*ROWQ + c4*4] =
            *(const float4*)&g_qf[((size_t)bh*T_ + tc*128 + rr)*HD + c4*4];
    }
    #pragma unroll
    for (int u = 0; u < 8; u++) {
        int f  = tid + u*128;
        int rr = f >> 4, c4 = f & 15;
        *(float4*)&kvb[rr*ROWQ + c4*4] =
            *(const float4*)&g_kvT[bh*HD*HD + rr*HD + c4*4];
    }
    if (tid < 64) sks[tid] = g_ksum[bh*HD + tid];
    __syncthreads();

    // denominator
    {
        float den = 0.f;
        #pragma unroll
        for (int d = 0; d < 64; d++) den += qa[tid*ROWQ + d] * sks[d];
        sden[tid] = 1.f / fmaxf(den, 1e-6f);
    }
    __syncthreads();

    const int mBase = wid * 32;
    const uint32_t aFrag0 = smem_u32(qa) +
        (uint32_t)(((mBase + (seg & 1)*8 + lrow)*ROWQ + (seg >> 1)*4) * 4);
    const uint32_t bFrag0 = smem_u32(kvb) +
        (uint32_t)((((seg >> 1)*8 + lrow)*ROWQ + (seg & 1)*4) * 4);

    float acc[2][8][4];
    #pragma unroll
    for (int mt = 0; mt < 2; mt++)
        #pragma unroll
        for (int nt = 0; nt < 8; nt++)
            #pragma unroll
            for (int q = 0; q < 4; q++) acc[mt][nt][q] = 0.f;

    const int krot = (wid & 3) * 16;   // anti-phase rotation across 4 warps
    #pragma unroll
    for (int kk = 0; kk < 64; kk += 8) {
        const uint32_t ks4 = (uint32_t)(((kk + krot) & 63) * 4);
        uint32_t af[2][4];
        uint32_t bf[4][4];
        ldsm_x4(af[0], aFrag0             + ks4);
        ldsm_x4(af[1], aFrag0 + 16*ROWQ*4 + ks4);
        #pragma unroll
        for (int p = 0; p < 4; p++)
            ldsm_x4(bf[p], bFrag0 + p*16*ROWQ*4 + ks4);
        #pragma unroll
        for (int mt = 0; mt < 2; mt++)
            #pragma unroll
            for (int nt = 0; nt < 8; nt++)
                mma_tf32(acc[mt][nt], af[mt], &bf[nt >> 1][(nt & 1)*2]);
    }

    // epilogue: scale by 1/den, tf32-round (feeds GEMM2), store to g_attn
    #pragma unroll
    for (int mt = 0; mt < 2; mt++) {
        const int rl0 = mBase + mt*16 + g;
        const float s0 = sden[rl0];
        const float s1 = sden[rl0 + 8];
        const int t0 = tc*128 + rl0;
        float* o0 = &g_attn[((size_t)(b*T_ + t0    ))*D_ + h*HD];
        float* o1 = &g_attn[((size_t)(b*T_ + t0 + 8))*D_ + h*HD];
        #pragma unroll
        for (int nt = 0; nt < 8; nt++) {
            const int c0 = nt*8 + tg*2;
            *(float2*)&o0[c0] = make_float2(tf32r(acc[mt][nt][0]*s0), tf32r(acc[mt][nt][1]*s0));
            *(float2*)&o1[c0] = make_float2(tf32r(acc[mt][nt][2]*s1), tf32r(acc[mt][nt][3]*s1));
        }
    }
}

// ---------------------------------------------------------------------------
extern "C" void kernel_launch(void* const* d_in, const int* in_sizes, int n_in,
                              void* d_out, int out_size) {
    const float* x = nullptr; const float* Wqkv = nullptr; const float* Wout = nullptr;
    for (int i = 0; i < n_in; i++) {
        if (in_sizes[i] == BT*D_)       x    = (const float*)d_in[i];
        else if (in_sizes[i] == D_*NKV) Wqkv = (const float*)d_in[i];
        else if (in_sizes[i] == D_*D_)  Wout = (const float*)d_in[i];
    }
    float* out = (float*)d_out;

    float *attn_p, *xa_p, *wqT_p, *woT_p;
    cudaGetSymbolAddress((void**)&attn_p, g_attn);
    cudaGetSymbolAddress((void**)&xa_p,   g_xa);
    cudaGetSymbolAddress((void**)&wqT_p,  g_wqT);
    cudaGetSymbolAddress((void**)&woT_p,  g_woT);

    cudaFuncSetAttribute(gemm_tf32_kernel,
                         cudaFuncAttributeMaxDynamicSharedMemorySize, GEMM_SMEM);
    cudaFuncSetAttribute(attn_mma_kernel,
                         cudaFuncAttributeMaxDynamicSharedMemorySize, ATT_SMEM);

    // launch 0: merged prep (tf32 round of x + fp32 RoPE tables)
    prep_kernel<<<RX_BLOCKS + RT_BLOCKS, 256>>>(x);
    // launch 1: weight transposes
    transpose_round_kernel<<<dim3(NKV/32 + D_/32, D_/32), dim3(32, 8)>>>(Wqkv, Wout);

    // launch 2: qkv GEMM with fused RoPE + feature-map epilogue
    gemm_tf32_kernel<<<dim3(NKV/128, BT/128), 256, GEMM_SMEM>>>(NKV, 1, xa_p, wqT_p, nullptr);

    // launch 3,4: kv & ksum (reduce emits transposed tf32 kvT)
    kv_accum_kernel<<<BH*NCHUNK, 128>>>();
    kv_reduce_kernel<<<(BH*HD*HD)/256 + (BH*HD + 255)/256, 256>>>();

    // launch 5: attention epilogue via tf32 MMA
    attn_mma_kernel<<<BH*32, 128, ATT_SMEM>>>();

    // launch 6: out = attn @ W_out
    gemm_tf32_kernel<<<dim3(D_/128, BT/128), 256, GEMM_SMEM>>>(D_, 0, attn_p, woT_p, out);
}

// round 15
// speedup vs baseline: 2.1007x; 1.0995x over previous
#include <cuda_runtime.h>
#include <math.h>
#include <stdint.h>

// Problem constants
#define B_   4
#define T_   4096
#define D_   1024
#define H_   16
#define HD   64
#define BT   (B_*T_)      // 16384
#define BH   (B_*H_)      // 64
#define NKV  3072
#define NCHUNK 32
#define CHLEN (T_/NCHUNK) // 128
#define GK   1024

// Scratch
__device__ float g_qf [BH*T_*HD];
__device__ float g_kf [BH*T_*HD];
__device__ float g_v  [BH*T_*HD];
__device__ float g_kvp[NCHUNK*BH*HD*HD];
__device__ float g_kvT[BH*HD*HD];    // kv transposed [bh][j][d], tf32-rounded
__device__ float g_ksp[NCHUNK*BH*HD];
__device__ float g_ksum[BH*HD];
__device__ float g_attn[BT*D_];
__device__ float g_wqT [NKV*D_];
__device__ float g_woT [D_*D_];
__device__ float g_cos[T_*32];
__device__ float g_sin[T_*32];

// ---------------------------------------------------------------------------
__device__ __forceinline__ uint32_t smem_u32(const void* p) {
    uint32_t a;
    asm("{ .reg .u64 t; cvta.to.shared.u64 t, %1; cvt.u32.u64 %0, t; }"
        : "=r"(a) : "l"(p));
    return a;
}
__device__ __forceinline__ float tf32r(float x) {
    uint32_t o;
    asm("cvt.rna.tf32.f32 %0, %1;" : "=r"(o) : "f"(x));
    return __uint_as_float(o);
}
#define CP_ASYNC16(dst, src) \
    asm volatile("cp.async.cg.shared.global [%0], [%1], 16;" :: "r"(dst), "l"(src) : "memory")
#define CP_COMMIT()  asm volatile("cp.async.commit_group;" ::: "memory")
#define CP_WAIT2()   asm volatile("cp.async.wait_group 2;" ::: "memory")

__device__ __forceinline__ void ldsm_x4(uint32_t* r, uint32_t addr) {
    asm volatile("ldmatrix.sync.aligned.m8n8.x4.shared.b16 {%0,%1,%2,%3}, [%4];"
        : "=r"(r[0]), "=r"(r[1]), "=r"(r[2]), "=r"(r[3]) : "r"(addr));
}
__device__ __forceinline__ void mma_tf32(float* d, const uint32_t* a, const uint32_t* b) {
    asm volatile(
        "mma.sync.aligned.m16n8k8.row.col.f32.tf32.tf32.f32 "
        "{%0,%1,%2,%3}, {%4,%5,%6,%7}, {%8,%9}, {%0,%1,%2,%3};"
        : "+f"(d[0]), "+f"(d[1]), "+f"(d[2]), "+f"(d[3])
        : "r"(a[0]), "r"(a[1]), "r"(a[2]), "r"(a[3]),
          "r"(b[0]), "r"(b[1]));
}
__device__ __forceinline__ float elu1(float x) {
    return x > 0.f ? x + 1.f : expf(x);
}

// ---------------------------------------------------------------------------
// tf32 mma.sync GEMM: 128x128 CTA tile, BK=16, 4-stage cp.async (wait_group 2)
// + barrier, 256 threads, warp tile 32x64, ldmatrix fragments, ROWF=20,
// anti-phase ks halves. Prefetch cp.async is issued BETWEEN the two MMA
// half-phases so LDGSTS/STS traffic overlaps tensor work (L1 and tensor are
// co-limited at ~50% each; this shifts STS wavefronts out of the LDSM phase).
// A operand may be raw fp32 — tf32 MMA HW ignores the 13 low mantissa bits.
// mode 0: plain C store. mode 1: fused RoPE/elu qkv epilogue (qf tf32-rounded).
// ---------------------------------------------------------------------------
#define STAGES 4
#define ROWF   20
#define STG_F  (128*ROWF)
#define GEMM_SMEM (2*STAGES*STG_F*4)    // 81920 B

__global__ __launch_bounds__(256, 2)
void gemm_tf32_kernel(int N, int mode, const float* __restrict__ A,
                      const float* __restrict__ Bt, float* __restrict__ C) {
    extern __shared__ float sm[];
    float* As = sm;
    float* Bs = sm + STAGES*STG_F;

    const int tid  = threadIdx.x;
    const int wid  = tid >> 5;
    const int lane = tid & 31;
    const int g    = lane >> 2;
    const int tg   = lane & 3;
    const int lrow = lane & 7;
    const int seg  = lane >> 3;      // 0..3

    const int rowBase = blockIdx.y * 128;
    const int colBase = blockIdx.x * 128;
    const int mBase = (wid & 3) * 32;
    const int nBase = (wid >> 2) * 64;

    // cp.async mapping: 2 threads per row, 8 floats (2x16B) each
    const int lr = tid >> 1;
    const int lc = (tid & 1) * 8;
    const float* aSrc = A  + (size_t)(rowBase + lr)*GK + lc;
    const float* bSrc = Bt + (size_t)(colBase + lr)*GK + lc;
    const uint32_t aDst = smem_u32(As) + (uint32_t)(lr*ROWF + lc)*4;
    const uint32_t bDst = smem_u32(Bs) + (uint32_t)(lr*ROWF + lc)*4;

    // ldmatrix per-lane base addresses
    const uint32_t aFrag0 = smem_u32(As) +
        (uint32_t)(((mBase + (seg & 1)*8 + lrow)*ROWF + (seg >> 1)*4) * 4);
    const uint32_t bFrag0 = smem_u32(Bs) +
        (uint32_t)(((nBase + (seg >> 1)*8 + lrow)*ROWF + (seg & 1)*4) * 4);

    // anti-phase ks byte offsets (ks=8 <-> 32 bytes)
    const uint32_t ksA = (wid & 1) ? 32u : 0u;
    const uint32_t ksB = ksA ^ 32u;

    float acc[2][8][4];
    #pragma unroll
    for (int mt = 0; mt < 2; mt++)
        #pragma unroll
        for (int nt = 0; nt < 8; nt++)
            #pragma unroll
            for (int q = 0; q < 4; q++) acc[mt][nt][q] = 0.f;

    // prologue: stages 0..2
    #pragma unroll
    for (int s = 0; s < STAGES-1; s++) {
        const uint32_t so = (uint32_t)s * (STG_F*4);
        const float* ap = aSrc + s*16;
        const float* bp = bSrc + s*16;
        CP_ASYNC16(aDst + so,      ap);
        CP_ASYNC16(aDst + so + 16, ap + 4);
        CP_ASYNC16(bDst + so,      bp);
        CP_ASYNC16(bDst + so + 16, bp + 4);
        CP_COMMIT();
    }

    const int NIT = GK / 16;   // 64
    for (int it = 0; it < NIT; it++) {
        CP_WAIT2();
        __syncthreads();

        const uint32_t so = (uint32_t)(it % STAGES) * (STG_F*4);
        const uint32_t aF = aFrag0 + so;
        const uint32_t bF = bFrag0 + so;

        // phase 1: this warp's first half-step (ksA)
        {
            uint32_t af[2][4], bf[4][4];
            ldsm_x4(af[0], aF             + ksA);
            ldsm_x4(af[1], aF + 16*ROWF*4 + ksA);
            #pragma unroll
            for (int p = 0; p < 4; p++)
                ldsm_x4(bf[p], bF + p*16*ROWF*4 + ksA);
            #pragma unroll
            for (int mt = 0; mt < 2; mt++)
                #pragma unroll
                for (int nt = 0; nt < 8; nt++)
                    mma_tf32(acc[mt][nt], af[mt], &bf[nt >> 1][(nt & 1)*2]);
        }

        // prefetch issued mid-iteration: LDGSTS/STS overlap tensor work
        const int nit = it + STAGES - 1;
        if (nit < NIT) {
            const int s = nit % STAGES;
            const uint32_t po = (uint32_t)s * (STG_F*4);
            const float* ap = aSrc + nit*16;
            const float* bp = bSrc + nit*16;
            CP_ASYNC16(aDst + po,      ap);
            CP_ASYNC16(aDst + po + 16, ap + 4);
            CP_ASYNC16(bDst + po,      bp);
            CP_ASYNC16(bDst + po + 16, bp + 4);
        }
        CP_COMMIT();

        // phase 2: the other half-step (ksB)
        {
            uint32_t af[2][4], bf[4][4];
            ldsm_x4(af[0], aF             + ksB);
            ldsm_x4(af[1], aF + 16*ROWF*4 + ksB);
            #pragma unroll
            for (int p = 0; p < 4; p++)
                ldsm_x4(bf[p], bF + p*16*ROWF*4 + ksB);
            #pragma unroll
            for (int mt = 0; mt < 2; mt++)
                #pragma unroll
                for (int nt = 0; nt < 8; nt++)
                    mma_tf32(acc[mt][nt], af[mt], &bf[nt >> 1][(nt & 1)*2]);
        }
    }

    if (mode == 0) {
        #pragma unroll
        for (int mt = 0; mt < 2; mt++) {
            const int r0 = rowBase + mBase + mt*16 + g;
            #pragma unroll
            for (int nt = 0; nt < 8; nt++) {
                const int c0 = colBase + nBase + nt*8 + tg*2;
                *(float2*)&C[(size_t) r0   *N + c0] = make_float2(acc[mt][nt][0], acc[mt][nt][1]);
                *(float2*)&C[(size_t)(r0+8)*N + c0] = make_float2(acc[mt][nt][2], acc[mt][nt][3]);
            }
        }
    } else {
        // fused qkv epilogue. Warp's 64 cols = one head of q, k, or v.
        const int region = colBase >> 10;            // 0=q 1=k 2=v
        float* dst = (region == 0) ? g_qf : (region == 1 ? g_kf : g_v);
        const int head = (((colBase & 1023) + nBase) >> 6);
        #pragma unroll
        for (int mt = 0; mt < 2; mt++) {
            #pragma unroll
            for (int half = 0; half < 2; half++) {
                const int row = rowBase + mBase + mt*16 + g + half*8;
                const int t = row & (T_-1);
                const int b = row >> 12;
                const size_t obase = ((size_t)(b*H_ + head)*T_ + t)*HD;
                #pragma unroll
                for (int nt = 0; nt < 4; nt++) {
                    const int i0 = nt*8 + tg*2;
                    const float a0 = acc[mt][nt  ][half*2+0];
                    const float a1 = acc[mt][nt  ][half*2+1];
                    const float b0 = acc[mt][nt+4][half*2+0];
                    const float b1 = acc[mt][nt+4][half*2+1];
                    if (region == 2) {
                        *(float2*)&dst[obase + i0]      = make_float2(a0, a1);
                        *(float2*)&dst[obase + i0 + 32] = make_float2(b0, b1);
                    } else {
                        const float2 cc = *(const float2*)&g_cos[t*32 + i0];
                        const float2 ss = *(const float2*)&g_sin[t*32 + i0];
                        float r10 = a0*cc.x - b0*ss.x, r20 = b0*cc.x + a0*ss.x;
                        float r11 = a1*cc.y - b1*ss.y, r21 = b1*cc.y + a1*ss.y;
                        if (region == 0) {
                            r10 *= 0.125f; r20 *= 0.125f; r11 *= 0.125f; r21 *= 0.125f;
                            *(float2*)&dst[obase + i0]      =
                                make_float2(tf32r(elu1(r10)), tf32r(elu1(r11)));
                            *(float2*)&dst[obase + i0 + 32] =
                                make_float2(tf32r(elu1(r20)), tf32r(elu1(r21)));
                        } else {
                            *(float2*)&dst[obase + i0]      = make_float2(elu1(r10), elu1(r11));
                            *(float2*)&dst[obase + i0 + 32] = make_float2(elu1(r20), elu1(r21));
                        }
                    }
                }
            }
        }
    }
}

// ---------------------------------------------------------------------------
// prep: RoPE tables only (x is consumed raw — tf32 HW truncation)
// ---------------------------------------------------------------------------
#define RT_BLOCKS (T_*32/256)       // 512

__global__ __launch_bounds__(256)
void prep_kernel() {
    int idx = blockIdx.x * 256 + threadIdx.x;
    int t = idx >> 5;
    int i = idx & 31;
    float inv = powf(500000.0f, -(float)i * (1.0f/32.0f));
    float a = (float)t * inv;
    g_cos[idx] = cosf(a);
    g_sin[idx] = sinf(a);
}

// both weight transposes in ONE launch
__global__ __launch_bounds__(256)
void transpose_round_kernel(const float* __restrict__ wq, const float* __restrict__ wo) {
    __shared__ float tile[32][33];
    const int R = D_;
    const float* in; float* out; int Cc; int bx;
    if (blockIdx.x < NKV/32) { in = wq; out = g_wqT; Cc = NKV; bx = blockIdx.x * 32; }
    else                     { in = wo; out = g_woT; Cc = D_;  bx = (blockIdx.x - NKV/32) * 32; }
    int by = blockIdx.y * 32;
    int tx = threadIdx.x, ty = threadIdx.y;
    #pragma unroll
    for (int i = 0; i < 32; i += 8)
        tile[ty + i][tx] = in[(size_t)(by + ty + i) * Cc + bx + tx];
    __syncthreads();
    #pragma unroll
    for (int i = 0; i < 32; i += 8)
        out[(size_t)(bx + ty + i) * R + by + tx] = tf32r(tile[tx][ty + i]);
}

// ---------------------------------------------------------------------------
// kv partial accumulation: 128 threads, 8x4 register microtile, NCHUNK=32
// ---------------------------------------------------------------------------
__global__ __launch_bounds__(128)
void kv_accum_kernel() {
    int blk = blockIdx.x;
    int bh  = blk >> 5;
    int c   = blk & 31;
    int tid = threadIdx.x;
    int d0  = (tid >> 4) * 8;     // 0..56
    int j0  = (tid & 15) * 4;     // 0..60

    __shared__ float kb[16][64];
    __shared__ float vb[16][64];

    float acc[8][4] = {};
    float ks[8] = {};

    int t0 = c * CHLEN;
    for (int tb = 0; tb < CHLEN; tb += 16) {
        #pragma unroll
        for (int u = 0; u < 2; u++) {
            int f  = tid + u*128;
            int rr = f >> 4, c4 = f & 15;
            int t  = t0 + tb + rr;
            *(float4*)&kb[rr][c4*4] =
                *(const float4*)&g_kf[((size_t)bh*T_ + t)*HD + c4*4];
            *(float4*)&vb[rr][c4*4] =
                *(const float4*)&g_v[((size_t)bh*T_ + t)*HD + c4*4];
        }
        __syncthreads();
        #pragma unroll
        for (int tt = 0; tt < 16; tt++) {
            float kk[8], vv[4];
            *(float4*)&kk[0] = *(float4*)&kb[tt][d0];
            *(float4*)&kk[4] = *(float4*)&kb[tt][d0+4];
            *(float4*)&vv[0] = *(float4*)&vb[tt][j0];
            #pragma unroll
            for (int i = 0; i < 8; i++) {
                ks[i] += kk[i];
                #pragma unroll
                for (int j = 0; j < 4; j++)
                    acc[i][j] += kk[i] * vv[j];
            }
        }
        __syncthreads();
    }

    #pragma unroll
    for (int i = 0; i < 8; i++) {
        float* p = &g_kvp[((size_t)(c*BH + bh)*HD + d0 + i)*HD + j0];
        *(float4*)p = make_float4(acc[i][0], acc[i][1], acc[i][2], acc[i][3]);
    }
    if ((tid & 15) == 0) {
        #pragma unroll
        for (int i = 0; i < 8; i++)
            g_ksp[(c*BH + bh)*HD + d0 + i] = ks[i];
    }
}

// kv reduce: blocks [0, 1024) reduce g_kvp -> g_kvT (transposed, tf32-rounded);
// blocks [1024, 1040) reduce g_ksp -> g_ksum.
__global__ void kv_reduce_kernel() {
    if (blockIdx.x < (BH*HD*HD)/256) {
        int idx = blockIdx.x * 256 + threadIdx.x;
        float s = 0.f;
        #pragma unroll
        for (int c = 0; c < NCHUNK; c++) s += g_kvp[(size_t)c*BH*HD*HD + idx];
        int j  = idx & 63;
        int d  = (idx >> 6) & 63;
        int bh = idx >> 12;
        g_kvT[bh*HD*HD + j*HD + d] = tf32r(s);
    } else {
        int idx = (blockIdx.x - (BH*HD*HD)/256) * 256 + threadIdx.x;
        if (idx < BH*HD) {
            float s = 0.f;
            #pragma unroll
            for (int c = 0; c < NCHUNK; c++) s += g_ksp[c*BH*HD + idx];
            g_ksum[idx] = s;
        }
    }
}

// ---------------------------------------------------------------------------
// attn numerator via tf32 MMA (R13 config + anti-phase ks rotation).
// ---------------------------------------------------------------------------
#define ROWQ 68
#define ATT_SMEM ((192*ROWQ + 64 + 128)*4)   // qa + kvb + sks + sden

__global__ __launch_bounds__(128)
void attn_mma_kernel() {
    extern __shared__ float sm[];
    float* qa  = sm;                  // [128][ROWQ]
    float* kvb = sm + 128*ROWQ;       // [64][ROWQ]
    float* sks = sm + 192*ROWQ;       // [64]
    float* sden= sks + 64;            // [128]

    const int blk = blockIdx.x;
    const int bh  = blk >> 5;
    const int tc  = blk & 31;
    const int b   = bh >> 4;
    const int h   = bh & 15;
    const int tid = threadIdx.x;
    const int wid = tid >> 5;
    const int lane = tid & 31;
    const int g    = lane >> 2;
    const int tg   = lane & 3;
    const int lrow = lane & 7;
    const int seg  = lane >> 3;

    // fill qa (128 rows x 64) and kvb (64 rows x 64), coalesced
    #pragma unroll
    for (int u = 0; u < 16; u++) {
        int f  = tid + u*128;
        int rr = f >> 4, c4 = f & 15;
        *(float4*)&qa[rr*ROWQ + c4*4] =
            *(const float4*)&g_qf[((size_t)bh*T_ + tc*128 + rr)*HD + c4*4];
    }
    #pragma unroll
    for (int u = 0; u < 8; u++) {
        int f  = tid + u*128;
        int rr = f >> 4, c4 = f & 15;
        *(float4*)&kvb[rr*ROWQ + c4*4] =
            *(const float4*)&g_kvT[bh*HD*HD + rr*HD + c4*4];
    }
    if (tid < 64) sks[tid] = g_ksum[bh*HD + tid];
    __syncthreads();

    // denominator
    {
        float den = 0.f;
        #pragma unroll
        for (int d = 0; d < 64; d++) den += qa[tid*ROWQ + d] * sks[d];
        sden[tid] = 1.f / fmaxf(den, 1e-6f);
    }
    __syncthreads();

    const int mBase = wid * 32;
    const uint32_t aFrag0 = smem_u32(qa) +
        (uint32_t)(((mBase + (seg & 1)*8 + lrow)*ROWQ + (seg >> 1)*4) * 4);
    const uint32_t bFrag0 = smem_u32(kvb) +
        (uint32_t)((((seg >> 1)*8 + lrow)*ROWQ + (seg & 1)*4) * 4);

    float acc[2][8][4];
    #pragma unroll
    for (int mt = 0; mt < 2; mt++)
        #pragma unroll
        for (int nt = 0; nt < 8; nt++)
            #pragma unroll
            for (int q = 0; q < 4; q++) acc[mt][nt][q] = 0.f;

    const int krot = (wid & 3) * 16;   // anti-phase rotation across 4 warps
    #pragma unroll
    for (int kk = 0; kk < 64; kk += 8) {
        const uint32_t ks4 = (uint32_t)(((kk + krot) & 63) * 4);
        uint32_t af[2][4];
        uint32_t bf[4][4];
        ldsm_x4(af[0], aFrag0             + ks4);
        ldsm_x4(af[1], aFrag0 + 16*ROWQ*4 + ks4);
        #pragma unroll
        for (int p = 0; p < 4; p++)
            ldsm_x4(bf[p], bFrag0 + p*16*ROWQ*4 + ks4);
        #pragma unroll
        for (int mt = 0; mt < 2; mt++)
            #pragma unroll
            for (int nt = 0; nt < 8; nt++)
                mma_tf32(acc[mt][nt], af[mt], &bf[nt >> 1][(nt & 1)*2]);
    }

    // epilogue: scale by 1/den, tf32-round (feeds GEMM2), store to g_attn
    #pragma unroll
    for (int mt = 0; mt < 2; mt++) {
        const int rl0 = mBase + mt*16 + g;
        const float s0 = sden[rl0];
        const float s1 = sden[rl0 + 8];
        const int t0 = tc*128 + rl0;
        float* o0 = &g_attn[((size_t)(b*T_ + t0    ))*D_ + h*HD];
        float* o1 = &g_attn[((size_t)(b*T_ + t0 + 8))*D_ + h*HD];
        #pragma unroll
        for (int nt = 0; nt < 8; nt++) {
            const int c0 = nt*8 + tg*2;
            *(float2*)&o0[c0] = make_float2(tf32r(acc[mt][nt][0]*s0), tf32r(acc[mt][nt][1]*s0));
            *(float2*)&o1[c0] = make_float2(tf32r(acc[mt][nt][2]*s1), tf32r(acc[mt][nt][3]*s1));
        }
    }
}

// ---------------------------------------------------------------------------
extern "C" void kernel_launch(void* const* d_in, const int* in_sizes, int n_in,
                              void* d_out, int out_size) {
    const float* x = nullptr; const float* Wqkv = nullptr; const float* Wout = nullptr;
    for (int i = 0; i < n_in; i++) {
        if (in_sizes[i] == BT*D_)       x    = (const float*)d_in[i];
        else if (in_sizes[i] == D_*NKV) Wqkv = (const float*)d_in[i];
        else if (in_sizes[i] == D_*D_)  Wout = (const float*)d_in[i];
    }
    float* out = (float*)d_out;

    float *attn_p, *wqT_p, *woT_p;
    cudaGetSymbolAddress((void**)&attn_p, g_attn);
    cudaGetSymbolAddress((void**)&wqT_p,  g_wqT);
    cudaGetSymbolAddress((void**)&woT_p,  g_woT);

    cudaFuncSetAttribute(gemm_tf32_kernel,
                         cudaFuncAttributeMaxDynamicSharedMemorySize, GEMM_SMEM);
    cudaFuncSetAttribute(attn_mma_kernel,
                         cudaFuncAttributeMaxDynamicSharedMemorySize, ATT_SMEM);

    // launch 0: RoPE tables
    prep_kernel<<<RT_BLOCKS, 256>>>();
    // launch 1: weight transposes (tf32-rounded)
    transpose_round_kernel<<<dim3(NKV/32 + D_/32, D_/32), dim3(32, 8)>>>(Wqkv, Wout);

    // launch 2: qkv GEMM (A = raw x; HW truncates to tf32) + fused RoPE/elu
    gemm_tf32_kernel<<<dim3(NKV/128, BT/128), 256, GEMM_SMEM>>>(NKV, 1, x, wqT_p, nullptr);

    // launch 3,4: kv & ksum (reduce emits transposed tf32 kvT)
    kv_accum_kernel<<<BH*NCHUNK, 128>>>();
    kv_reduce_kernel<<<(BH*HD*HD)/256 + (BH*HD + 255)/256, 256>>>();

    // launch 5: attention epilogue via tf32 MMA
    attn_mma_kernel<<<BH*32, 128, ATT_SMEM>>>();

    // launch 6: out = attn @ W_out
    gemm_tf32_kernel<<<dim3(D_/128, BT/128), 256, GEMM_SMEM>>>(D_, 0, attn_p, woT_p, out);
}

// round 16
// speedup vs baseline: 2.7204x; 1.2950x over previous
#include <cuda_runtime.h>
#include <cuda_fp16.h>
#include <math.h>
#include <stdint.h>

// Problem constants
#define B_   4
#define T_   4096
#define D_   1024
#define H_   16
#define HD   64
#define BT   (B_*T_)      // 16384
#define BH   (B_*H_)      // 64
#define NKV  3072
#define NCHUNK 32
#define CHLEN (T_/NCHUNK) // 128
#define GK   1024

// Scratch
__device__ __half g_xh  [BT*D_];     // x in fp16
__device__ __half g_qfh [BH*T_*HD];  // q feature map, fp16
__device__ float  g_kf  [BH*T_*HD];  // k feature map, fp32 (kv accumulation)
__device__ float  g_v   [BH*T_*HD];
__device__ float  g_kvp [NCHUNK*BH*HD*HD];
__device__ __half g_kvTh[BH*HD*HD];  // kv transposed [bh][j][d], fp16
__device__ float  g_ksp [NCHUNK*BH*HD];
__device__ float  g_ksum[BH*HD];
__device__ __half g_attnh[BT*D_];    // attn output, fp16 (feeds GEMM2)
__device__ __half g_wqTh[NKV*D_];    // Wqkv^T fp16
__device__ __half g_woTh[D_*D_];     // Wout^T fp16
__device__ float  g_cos[T_*32];
__device__ float  g_sin[T_*32];

// ---------------------------------------------------------------------------
__device__ __forceinline__ uint32_t smem_u32(const void* p) {
    uint32_t a;
    asm("{ .reg .u64 t; cvta.to.shared.u64 t, %1; cvt.u32.u64 %0, t; }"
        : "=r"(a) : "l"(p));
    return a;
}
#define CP_ASYNC16(dst, src) \
    asm volatile("cp.async.cg.shared.global [%0], [%1], 16;" :: "r"(dst), "l"(src) : "memory")
#define CP_COMMIT()  asm volatile("cp.async.commit_group;" ::: "memory")
#define CP_WAIT2()   asm volatile("cp.async.wait_group 2;" ::: "memory")

__device__ __forceinline__ void ldsm_x4(uint32_t* r, uint32_t addr) {
    asm volatile("ldmatrix.sync.aligned.m8n8.x4.shared.b16 {%0,%1,%2,%3}, [%4];"
        : "=r"(r[0]), "=r"(r[1]), "=r"(r[2]), "=r"(r[3]) : "r"(addr));
}
// fp16 MMA: m16n8k16, fp32 accumulate
__device__ __forceinline__ void mma_f16(float* d, const uint32_t* a, const uint32_t* b) {
    asm volatile(
        "mma.sync.aligned.m16n8k16.row.col.f32.f16.f16.f32 "
        "{%0,%1,%2,%3}, {%4,%5,%6,%7}, {%8,%9}, {%0,%1,%2,%3};"
        : "+f"(d[0]), "+f"(d[1]), "+f"(d[2]), "+f"(d[3])
        : "r"(a[0]), "r"(a[1]), "r"(a[2]), "r"(a[3]),
          "r"(b[0]), "r"(b[1]));
}
__device__ __forceinline__ float elu1(float x) {
    return x > 0.f ? x + 1.f : expf(x);
}
__device__ __forceinline__ uint32_t pack_h2(float a, float b) {
    __half2 h = __floats2half2_rn(a, b);
    return *(uint32_t*)&h;
}

// ---------------------------------------------------------------------------
// fp16 mma.sync GEMM: 128x128 CTA tile, BK=32 halfs per stage (same 80B/row as
// the tf32 ROWF=20 layout -> identical conflict-free quad permutation), 4-stage
// cp.async + barrier, 256 threads, warp tile 32x64, anti-phase k16 halves,
// prefetch between half-phases. 32 iterations (half of tf32 BK=16).
// mode 0: plain fp32 C store. mode 1: fused RoPE/elu qkv epilogue.
// ---------------------------------------------------------------------------
#define STAGES 4
#define ROWH   40                       // halfs per padded row (64B data + 16B pad)
#define STG_H  (128*ROWH)               // halfs per tile per stage
#define GEMM_SMEM (2*STAGES*STG_H*2)    // 81920 B

__global__ __launch_bounds__(256, 2)
void gemm_f16_kernel(int N, int mode, const __half* __restrict__ A,
                     const __half* __restrict__ Bt, float* __restrict__ C) {
    extern __shared__ __half smh[];
    __half* As = smh;
    __half* Bs = smh + STAGES*STG_H;

    const int tid  = threadIdx.x;
    const int wid  = tid >> 5;
    const int lane = tid & 31;
    const int g    = lane >> 2;
    const int tg   = lane & 3;
    const int lrow = lane & 7;
    const int seg  = lane >> 3;      // 0..3

    const int rowBase = blockIdx.y * 128;
    const int colBase = blockIdx.x * 128;
    const int mBase = (wid & 3) * 32;
    const int nBase = (wid >> 2) * 64;

    // cp.async mapping: row = tid&127, two 16B segments per thread per tile
    const int crow = tid & 127;
    const int s0   = tid >> 7;           // first seg: 0 or 1 (second = s0+2)
    const __half* aSrc = A  + (size_t)(rowBase + crow)*GK;
    const __half* bSrc = Bt + (size_t)(colBase + crow)*GK;
    const uint32_t aDst = smem_u32(As) + (uint32_t)(crow*ROWH)*2;
    const uint32_t bDst = smem_u32(Bs) + (uint32_t)(crow*ROWH)*2;

    // ldmatrix per-lane base addresses (byte offsets)
    const uint32_t aFrag0 = smem_u32(As) +
        (uint32_t)(((mBase + (seg & 1)*8 + lrow)*ROWH + (seg >> 1)*8) * 2);
    const uint32_t bFrag0 = smem_u32(Bs) +
        (uint32_t)(((nBase + (seg >> 1)*8 + lrow)*ROWH + (seg & 1)*8) * 2);

    // anti-phase k16 byte offsets (16 halfs = 32B)
    const uint32_t ksA = (wid & 1) ? 32u : 0u;
    const uint32_t ksB = ksA ^ 32u;

    float acc[2][8][4];
    #pragma unroll
    for (int mt = 0; mt < 2; mt++)
        #pragma unroll
        for (int nt = 0; nt < 8; nt++)
            #pragma unroll
            for (int q = 0; q < 4; q++) acc[mt][nt][q] = 0.f;

    // prologue: stages 0..2
    #pragma unroll
    for (int s = 0; s < STAGES-1; s++) {
        const uint32_t so = (uint32_t)s * (STG_H*2);
        const __half* ap = aSrc + s*32;
        const __half* bp = bSrc + s*32;
        CP_ASYNC16(aDst + so + 16*s0,      ap + 8*s0);
        CP_ASYNC16(aDst + so + 16*(s0+2),  ap + 8*(s0+2));
        CP_ASYNC16(bDst + so + 16*s0,      bp + 8*s0);
        CP_ASYNC16(bDst + so + 16*(s0+2),  bp + 8*(s0+2));
        CP_COMMIT();
    }

    const int NIT = GK / 32;   // 32
    for (int it = 0; it < NIT; it++) {
        CP_WAIT2();
        __syncthreads();

        const uint32_t so = (uint32_t)(it % STAGES) * (STG_H*2);
        const uint32_t aF = aFrag0 + so;
        const uint32_t bF = bFrag0 + so;

        // phase 1: this warp's first k16 half (ksA)
        {
            uint32_t af[2][4], bf[4][4];
            ldsm_x4(af[0], aF             + ksA);
            ldsm_x4(af[1], aF + 16*ROWH*2 + ksA);
            #pragma unroll
            for (int p = 0; p < 4; p++)
                ldsm_x4(bf[p], bF + p*16*ROWH*2 + ksA);
            #pragma unroll
            for (int mt = 0; mt < 2; mt++)
                #pragma unroll
                for (int nt = 0; nt < 8; nt++)
                    mma_f16(acc[mt][nt], af[mt], &bf[nt >> 1][(nt & 1)*2]);
        }

        // prefetch between half-phases (overlaps tensor work)
        const int nit = it + STAGES - 1;
        if (nit < NIT) {
            const int s = nit % STAGES;
            const uint32_t po = (uint32_t)s * (STG_H*2);
            const __half* ap = aSrc + nit*32;
            const __half* bp = bSrc + nit*32;
            CP_ASYNC16(aDst + po + 16*s0,      ap + 8*s0);
            CP_ASYNC16(aDst + po + 16*(s0+2),  ap + 8*(s0+2));
            CP_ASYNC16(bDst + po + 16*s0,      bp + 8*s0);
            CP_ASYNC16(bDst + po + 16*(s0+2),  bp + 8*(s0+2));
        }
        CP_COMMIT();

        // phase 2: the other k16 half (ksB)
        {
            uint32_t af[2][4], bf[4][4];
            ldsm_x4(af[0], aF             + ksB);
            ldsm_x4(af[1], aF + 16*ROWH*2 + ksB);
            #pragma unroll
            for (int p = 0; p < 4; p++)
                ldsm_x4(bf[p], bF + p*16*ROWH*2 + ksB);
            #pragma unroll
            for (int mt = 0; mt < 2; mt++)
                #pragma unroll
                for (int nt = 0; nt < 8; nt++)
                    mma_f16(acc[mt][nt], af[mt], &bf[nt >> 1][(nt & 1)*2]);
        }
    }

    if (mode == 0) {
        #pragma unroll
        for (int mt = 0; mt < 2; mt++) {
            const int r0 = rowBase + mBase + mt*16 + g;
            #pragma unroll
            for (int nt = 0; nt < 8; nt++) {
                const int c0 = colBase + nBase + nt*8 + tg*2;
                *(float2*)&C[(size_t) r0   *N + c0] = make_float2(acc[mt][nt][0], acc[mt][nt][1]);
                *(float2*)&C[(size_t)(r0+8)*N + c0] = make_float2(acc[mt][nt][2], acc[mt][nt][3]);
            }
        }
    } else {
        // fused qkv epilogue. Warp's 64 cols = one head of q, k, or v.
        const int region = colBase >> 10;            // 0=q 1=k 2=v
        const int head = (((colBase & 1023) + nBase) >> 6);
        #pragma unroll
        for (int mt = 0; mt < 2; mt++) {
            #pragma unroll
            for (int half_ = 0; half_ < 2; half_++) {
                const int row = rowBase + mBase + mt*16 + g + half_*8;
                const int t = row & (T_-1);
                const int b = row >> 12;
                const size_t obase = ((size_t)(b*H_ + head)*T_ + t)*HD;
                #pragma unroll
                for (int nt = 0; nt < 4; nt++) {
                    const int i0 = nt*8 + tg*2;
                    const float a0 = acc[mt][nt  ][half_*2+0];
                    const float a1 = acc[mt][nt  ][half_*2+1];
                    const float b0 = acc[mt][nt+4][half_*2+0];
                    const float b1 = acc[mt][nt+4][half_*2+1];
                    if (region == 2) {
                        *(float2*)&g_v[obase + i0]      = make_float2(a0, a1);
                        *(float2*)&g_v[obase + i0 + 32] = make_float2(b0, b1);
                    } else {
                        const float2 cc = *(const float2*)&g_cos[t*32 + i0];
                        const float2 ss = *(const float2*)&g_sin[t*32 + i0];
                        float r10 = a0*cc.x - b0*ss.x, r20 = b0*cc.x + a0*ss.x;
                        float r11 = a1*cc.y - b1*ss.y, r21 = b1*cc.y + a1*ss.y;
                        if (region == 0) {
                            r10 *= 0.125f; r20 *= 0.125f; r11 *= 0.125f; r21 *= 0.125f;
                            *(uint32_t*)&g_qfh[obase + i0]      = pack_h2(elu1(r10), elu1(r11));
                            *(uint32_t*)&g_qfh[obase + i0 + 32] = pack_h2(elu1(r20), elu1(r21));
                        } else {
                            *(float2*)&g_kf[obase + i0]      = make_float2(elu1(r10), elu1(r11));
                            *(float2*)&g_kf[obase + i0 + 32] = make_float2(elu1(r20), elu1(r21));
                        }
                    }
                }
            }
        }
    }
}

// ---------------------------------------------------------------------------
// merged prep: blocks [0, XH_BLOCKS) convert x->fp16; rest build RoPE tables
// ---------------------------------------------------------------------------
#define XH_BLOCKS (BT*D_/4/256)     // 16384 (4 floats per thread)
#define RT_BLOCKS (T_*32/256)       // 512

__global__ __launch_bounds__(256)
void prep_kernel(const float* __restrict__ x) {
    if (blockIdx.x < XH_BLOCKS) {
        int i = blockIdx.x * 256 + threadIdx.x;
        float4 v = ((const float4*)x)[i];
        uint2 o;
        o.x = pack_h2(v.x, v.y);
        o.y = pack_h2(v.z, v.w);
        ((uint2*)g_xh)[i] = o;
    } else {
        int idx = (blockIdx.x - XH_BLOCKS) * 256 + threadIdx.x;
        int t = idx >> 5;
        int i = idx & 31;
        float inv = powf(500000.0f, -(float)i * (1.0f/32.0f));
        float a = (float)t * inv;
        g_cos[idx] = cosf(a);
        g_sin[idx] = sinf(a);
    }
}

// both weight transposes (fp32 -> fp16) in ONE launch
__global__ __launch_bounds__(256)
void transpose_half_kernel(const float* __restrict__ wq, const float* __restrict__ wo) {
    __shared__ float tile[32][33];
    const int R = D_;
    const float* in; __half* out; int Cc; int bx;
    if (blockIdx.x < NKV/32) { in = wq; out = g_wqTh; Cc = NKV; bx = blockIdx.x * 32; }
    else                     { in = wo; out = g_woTh; Cc = D_;  bx = (blockIdx.x - NKV/32) * 32; }
    int by = blockIdx.y * 32;
    int tx = threadIdx.x, ty = threadIdx.y;
    #pragma unroll
    for (int i = 0; i < 32; i += 8)
        tile[ty + i][tx] = in[(size_t)(by + ty + i) * Cc + bx + tx];
    __syncthreads();
    #pragma unroll
    for (int i = 0; i < 32; i += 8)
        out[(size_t)(bx + ty + i) * R + by + tx] = __float2half_rn(tile[tx][ty + i]);
}

// ---------------------------------------------------------------------------
// kv partial accumulation: 128 threads, 8x4 register microtile, NCHUNK=32
// (fp32 path — long-T accumulation stays full precision)
// ---------------------------------------------------------------------------
__global__ __launch_bounds__(128)
void kv_accum_kernel() {
    int blk = blockIdx.x;
    int bh  = blk >> 5;
    int c   = blk & 31;
    int tid = threadIdx.x;
    int d0  = (tid >> 4) * 8;     // 0..56
    int j0  = (tid & 15) * 4;     // 0..60

    __shared__ float kb[16][64];
    __shared__ float vb[16][64];

    float acc[8][4] = {};
    float ks[8] = {};

    int t0 = c * CHLEN;
    for (int tb = 0; tb < CHLEN; tb += 16) {
        #pragma unroll
        for (int u = 0; u < 2; u++) {
            int f  = tid + u*128;
            int rr = f >> 4, c4 = f & 15;
            int t  = t0 + tb + rr;
            *(float4*)&kb[rr][c4*4] =
                *(const float4*)&g_kf[((size_t)bh*T_ + t)*HD + c4*4];
            *(float4*)&vb[rr][c4*4] =
                *(const float4*)&g_v[((size_t)bh*T_ + t)*HD + c4*4];
        }
        __syncthreads();
        #pragma unroll
        for (int tt = 0; tt < 16; tt++) {
            float kk[8], vv[4];
            *(float4*)&kk[0] = *(float4*)&kb[tt][d0];
            *(float4*)&kk[4] = *(float4*)&kb[tt][d0+4];
            *(float4*)&vv[0] = *(float4*)&vb[tt][j0];
            #pragma unroll
            for (int i = 0; i < 8; i++) {
                ks[i] += kk[i];
                #pragma unroll
                for (int j = 0; j < 4; j++)
                    acc[i][j] += kk[i] * vv[j];
            }
        }
        __syncthreads();
    }

    #pragma unroll
    for (int i = 0; i < 8; i++) {
        float* p = &g_kvp[((size_t)(c*BH + bh)*HD + d0 + i)*HD + j0];
        *(float4*)p = make_float4(acc[i][0], acc[i][1], acc[i][2], acc[i][3]);
    }
    if ((tid & 15) == 0) {
        #pragma unroll
        for (int i = 0; i < 8; i++)
            g_ksp[(c*BH + bh)*HD + d0 + i] = ks[i];
    }
}

// kv reduce -> g_kvTh (transposed fp16) and g_ksum
__global__ void kv_reduce_kernel() {
    if (blockIdx.x < (BH*HD*HD)/256) {
        int idx = blockIdx.x * 256 + threadIdx.x;
        float s = 0.f;
        #pragma unroll
        for (int c = 0; c < NCHUNK; c++) s += g_kvp[(size_t)c*BH*HD*HD + idx];
        int j  = idx & 63;
        int d  = (idx >> 6) & 63;
        int bh = idx >> 12;
        g_kvTh[bh*HD*HD + j*HD + d] = __float2half_rn(s);
    } else {
        int idx = (blockIdx.x - (BH*HD*HD)/256) * 256 + threadIdx.x;
        if (idx < BH*HD) {
            float s = 0.f;
            #pragma unroll
            for (int c = 0; c < NCHUNK; c++) s += g_ksp[c*BH*HD + idx];
            g_ksum[idx] = s;
        }
    }
}

// ---------------------------------------------------------------------------
// attn numerator via fp16 MMA: out[t][j] = (qf[t,:] @ kvT[j,:]) / den(t).
// ROWQ=72 halfs (144B row = 9x16B: quad perm r mod 8, conflict-free).
// K=64 -> 4 k16 steps, anti-phase rotation across 4 warps.
// Output stored fp16 (feeds GEMM2).
// ---------------------------------------------------------------------------
#define ROWQ 72
#define ATT_SMEM ((192*ROWQ)*2 + (64 + 128)*4)

__global__ __launch_bounds__(128)
void attn_mma_kernel() {
    extern __shared__ __half smq[];
    __half* qa  = smq;                    // [128][ROWQ]
    __half* kvb = smq + 128*ROWQ;         // [64][ROWQ]
    float* sks  = (float*)(smq + 192*ROWQ);  // [64]
    float* sden = sks + 64;                  // [128]

    const int blk = blockIdx.x;
    const int bh  = blk >> 5;
    const int tc  = blk & 31;
    const int b   = bh >> 4;
    const int h   = bh & 15;
    const int tid = threadIdx.x;
    const int wid = tid >> 5;
    const int lane = tid & 31;
    const int g    = lane >> 2;
    const int tg   = lane & 3;
    const int lrow = lane & 7;
    const int seg  = lane >> 3;

    // fill qa (128 rows x 64 halfs) and kvb (64 rows x 64 halfs), 16B chunks
    #pragma unroll
    for (int u = 0; u < 8; u++) {
        int f  = tid + u*128;          // 0..1023
        int rr = f >> 3, sg = f & 7;
        *(uint4*)&qa[rr*ROWQ + sg*8] =
            *(const uint4*)&g_qfh[((size_t)bh*T_ + tc*128 + rr)*HD + sg*8];
    }
    #pragma unroll
    for (int u = 0; u < 4; u++) {
        int f  = tid + u*128;          // 0..511
        int rr = f >> 3, sg = f & 7;
        *(uint4*)&kvb[rr*ROWQ + sg*8] =
            *(const uint4*)&g_kvTh[bh*HD*HD + rr*HD + sg*8];
    }
    if (tid < 64) sks[tid] = g_ksum[bh*HD + tid];
    __syncthreads();

    // denominator (fp32 dot over fp16 qf)
    {
        float den = 0.f;
        #pragma unroll
        for (int d = 0; d < 32; d++) {
            __half2 q2 = *(const __half2*)&qa[tid*ROWQ + d*2];
            float2 qf2 = __half22float2(q2);
            den += qf2.x * sks[d*2] + qf2.y * sks[d*2+1];
        }
        sden[tid] = 1.f / fmaxf(den, 1e-6f);
    }
    __syncthreads();

    const int mBase = wid * 32;
    const uint32_t aFrag0 = smem_u32(qa) +
        (uint32_t)(((mBase + (seg & 1)*8 + lrow)*ROWQ + (seg >> 1)*8) * 2);
    const uint32_t bFrag0 = smem_u32(kvb) +
        (uint32_t)((((seg >> 1)*8 + lrow)*ROWQ + (seg & 1)*8) * 2);

    float acc[2][8][4];
    #pragma unroll
    for (int mt = 0; mt < 2; mt++)
        #pragma unroll
        for (int nt = 0; nt < 8; nt++)
            #pragma unroll
            for (int q = 0; q < 4; q++) acc[mt][nt][q] = 0.f;

    const int krot = wid & 3;
    #pragma unroll
    for (int kk = 0; kk < 4; kk++) {
        const uint32_t ks = (uint32_t)(((kk + krot) & 3) * 32);  // 16 halfs = 32B
        uint32_t af[2][4];
        uint32_t bf[4][4];
        ldsm_x4(af[0], aFrag0             + ks);
        ldsm_x4(af[1], aFrag0 + 16*ROWQ*2 + ks);
        #pragma unroll
        for (int p = 0; p < 4; p++)
            ldsm_x4(bf[p], bFrag0 + p*16*ROWQ*2 + ks);
        #pragma unroll
        for (int mt = 0; mt < 2; mt++)
            #pragma unroll
            for (int nt = 0; nt < 8; nt++)
                mma_f16(acc[mt][nt], af[mt], &bf[nt >> 1][(nt & 1)*2]);
    }

    // epilogue: scale by 1/den, store fp16 to g_attnh
    #pragma unroll
    for (int mt = 0; mt < 2; mt++) {
        const int rl0 = mBase + mt*16 + g;
        const float s0 = sden[rl0];
        const float s1 = sden[rl0 + 8];
        const int t0 = tc*128 + rl0;
        __half* o0 = &g_attnh[((size_t)(b*T_ + t0    ))*D_ + h*HD];
        __half* o1 = &g_attnh[((size_t)(b*T_ + t0 + 8))*D_ + h*HD];
        #pragma unroll
        for (int nt = 0; nt < 8; nt++) {
            const int c0 = nt*8 + tg*2;
            *(uint32_t*)&o0[c0] = pack_h2(acc[mt][nt][0]*s0, acc[mt][nt][1]*s0);
            *(uint32_t*)&o1[c0] = pack_h2(acc[mt][nt][2]*s1, acc[mt][nt][3]*s1);
        }
    }
}

// ---------------------------------------------------------------------------
extern "C" void kernel_launch(void* const* d_in, const int* in_sizes, int n_in,
                              void* d_out, int out_size) {
    const float* x = nullptr; const float* Wqkv = nullptr; const float* Wout = nullptr;
    for (int i = 0; i < n_in; i++) {
        if (in_sizes[i] == BT*D_)       x    = (const float*)d_in[i];
        else if (in_sizes[i] == D_*NKV) Wqkv = (const float*)d_in[i];
        else if (in_sizes[i] == D_*D_)  Wout = (const float*)d_in[i];
    }
    float* out = (float*)d_out;

    __half *xh_p, *attnh_p, *wqTh_p, *woTh_p;
    cudaGetSymbolAddress((void**)&xh_p,    g_xh);
    cudaGetSymbolAddress((void**)&attnh_p, g_attnh);
    cudaGetSymbolAddress((void**)&wqTh_p,  g_wqTh);
    cudaGetSymbolAddress((void**)&woTh_p,  g_woTh);

    cudaFuncSetAttribute(gemm_f16_kernel,
                         cudaFuncAttributeMaxDynamicSharedMemorySize, GEMM_SMEM);
    cudaFuncSetAttribute(attn_mma_kernel,
                         cudaFuncAttributeMaxDynamicSharedMemorySize, ATT_SMEM);

    // launch 0: prep (x->fp16 + RoPE tables)
    prep_kernel<<<XH_BLOCKS + RT_BLOCKS, 256>>>(x);
    // launch 1: weight transposes -> fp16
    transpose_half_kernel<<<dim3(NKV/32 + D_/32, D_/32), dim3(32, 8)>>>(Wqkv, Wout);

    // launch 2: qkv GEMM (fp16) + fused RoPE/elu epilogue
    gemm_f16_kernel<<<dim3(NKV/128, BT/128), 256, GEMM_SMEM>>>(NKV, 1, xh_p, wqTh_p, nullptr);

    // launch 3,4: kv & ksum (fp32 accumulation; reduce emits fp16 kvT)
    kv_accum_kernel<<<BH*NCHUNK, 128>>>();
    kv_reduce_kernel<<<(BH*HD*HD)/256 + (BH*HD + 255)/256, 256>>>();

    // launch 5: attention epilogue via fp16 MMA -> g_attnh
    attn_mma_kernel<<<BH*32, 128, ATT_SMEM>>>();

    // launch 6: out = attn @ W_out (fp16 GEMM, fp32 out)
    gemm_f16_kernel<<<dim3(D_/128, BT/128), 256, GEMM_SMEM>>>(D_, 0, attnh_p, woTh_p, out);
}